// round 10
// baseline (speedup 1.0000x reference)
#include <cuda_runtime.h>
#include <cuda_bf16.h>
#include <math.h>

#define EMBD   256
#define HEADS  16
#define DHEAD  16
#define BATCH  64
#define MROWS  128
#define JJOBS  512
#define TTOK   513
#define OUT_PER_B (MROWS * TTOK)   // 65664

typedef unsigned long long ull;

__device__ float g_Q [BATCH * MROWS * EMBD];
__device__ float g_K [BATCH * TTOK  * EMBD];
__device__ float g_V [BATCH * TTOK  * EMBD];
__device__ float g_O [BATCH * MROWS * EMBD];
__device__ float g_MH[BATCH * MROWS * EMBD];
__device__ float g_SUM[BATCH];

// ---------------- packed f32x2 helpers (sm_103a) ----------------
__device__ __forceinline__ ull fma2(ull a, ull b, ull c) {
    ull d; asm("fma.rn.f32x2 %0, %1, %2, %3;" : "=l"(d) : "l"(a), "l"(b), "l"(c));
    return d;
}
__device__ __forceinline__ ull mul2(ull a, ull b) {
    ull d; asm("mul.rn.f32x2 %0, %1, %2;" : "=l"(d) : "l"(a), "l"(b));
    return d;
}
__device__ __forceinline__ ull bcast2(float x) {
    ull d; asm("mov.b64 %0, {%1, %2};" : "=l"(d) : "f"(x), "f"(x));
    return d;
}
__device__ __forceinline__ float2 unpack2(ull v) {
    float2 f; asm("mov.b64 {%0, %1}, %2;" : "=f"(f.x), "=f"(f.y) : "l"(v));
    return f;
}

// exact-enough tanh: (1 - 2/(e^{2x}+1)); err ~1e-6
__device__ __forceinline__ float tanh_fast(float x) {
    const float e = __expf(2.0f * x);
    return 1.0f - __fdividef(2.0f, e + 1.0f);
}

__device__ __forceinline__ const float* jobs_row(const float* __restrict__ jobs,
                                                 const float* __restrict__ skip,
                                                 int b, int t) {
    return (t == 0) ? skip : jobs + ((long)b * JJOBS + (t - 1)) * EMBD;
}

// =================== tiles ===================
#define BM 128
#define BN 128
#define BK 16

// dup-A microkernel, BK=16: A pairs pre-duplicated in smem, no inner MOVs
#define GEMM_MICRO_DUP16(cur)                                                  \
    _Pragma("unroll")                                                          \
    for (int kk = 0; kk < BK; kk++) {                                          \
        ulonglong2 qa = *(const ulonglong2*)&As2[cur][kk][ty * 4];             \
        ulonglong2 qb = *(const ulonglong2*)&As2[cur][kk][ty * 4 + 2];         \
        ulonglong2 qc = *(const ulonglong2*)&As2[cur][kk][64 + ty * 4];        \
        ulonglong2 qd = *(const ulonglong2*)&As2[cur][kk][64 + ty * 4 + 2];    \
        ulonglong2 p0 = *(const ulonglong2*)&Bs[cur][kk][tx * 4];              \
        ulonglong2 p1 = *(const ulonglong2*)&Bs[cur][kk][64 + tx * 4];         \
        ull A2[8] = {qa.x, qa.y, qb.x, qb.y, qc.x, qc.y, qd.x, qd.y};          \
        ull B2[4] = {p0.x, p0.y, p1.x, p1.y};                                  \
        _Pragma("unroll")                                                      \
        for (int i = 0; i < 8; i++)                                            \
            _Pragma("unroll")                                                  \
            for (int j = 0; j < 4; j++)                                        \
                acc2[i][j] = fma2(A2[i], B2[j], acc2[i][j]);                   \
    }

// =================== merged projection kernel (Q, K, V), dup-A BK=16 =======
__global__ void __launch_bounds__(256, 2)
proj_kernel(const float* __restrict__ jobs, const float* __restrict__ skip,
            const float* __restrict__ machine,
            const float* __restrict__ Wk, const float* __restrict__ Wv,
            const float* __restrict__ Wq,
            float* __restrict__ Kout, float* __restrict__ Vout,
            float* __restrict__ Qout, float* __restrict__ sums)
{
    __shared__ ull   As2[2][BK][BM];    // duplicated (v,v) pairs: 32 KB
    __shared__ float Bs [2][BK][BN];    // 16 KB

    const int z = blockIdx.z;
    const int row0 = blockIdx.y * BM;
    const int nrows = (z == 2) ? (BATCH * MROWS) : (BATCH * TTOK);

    if (z == 2 && blockIdx.x == 0 && blockIdx.y == 0 && threadIdx.x < BATCH)
        sums[threadIdx.x] = 0.0f;
    if (row0 >= nrows) return;

    const float* W = (z == 0) ? Wk : (z == 1) ? Wv : Wq;
    float*       C = (z == 0) ? Kout : (z == 1) ? Vout : Qout;

    const int tid  = threadIdx.x;
    const int col0 = blockIdx.x * BN;

    const int a_row = tid >> 1;          // 0..127
    const int a_k   = (tid & 1) * 8;     // 0 or 8
    const int b_k   = tid >> 4;          // 0..15
    const int b_n   = (tid & 15) * 8;    // 0..120
    const int tx = tid & 15;
    const int ty = tid >> 4;

    const float* xrow;
    {
        int grow = row0 + a_row;
        if (grow > nrows - 1) grow = nrows - 1;
        if (z == 2) {
            xrow = machine + (long)grow * EMBD;
        } else {
            const int b = grow / TTOK;
            const int t = grow - b * TTOK;
            xrow = jobs_row(jobs, skip, b, t);
        }
    }
    const float* wptr = W + (long)b_k * EMBD + col0 + b_n;

    float4 av0, av1, bv0, bv1;
    av0 = *(const float4*)(xrow + a_k);
    av1 = *(const float4*)(xrow + a_k + 4);
    bv0 = *(const float4*)(wptr);
    bv1 = *(const float4*)(wptr + 4);
    As2[0][a_k + 0][a_row] = bcast2(av0.x);
    As2[0][a_k + 1][a_row] = bcast2(av0.y);
    As2[0][a_k + 2][a_row] = bcast2(av0.z);
    As2[0][a_k + 3][a_row] = bcast2(av0.w);
    As2[0][a_k + 4][a_row] = bcast2(av1.x);
    As2[0][a_k + 5][a_row] = bcast2(av1.y);
    As2[0][a_k + 6][a_row] = bcast2(av1.z);
    As2[0][a_k + 7][a_row] = bcast2(av1.w);
    *(float4*)&Bs[0][b_k][b_n]     = bv0;
    *(float4*)&Bs[0][b_k][b_n + 4] = bv1;
    __syncthreads();

    ull acc2[8][4] = {};

    #pragma unroll 1
    for (int ks = 0; ks < EMBD / BK; ks++) {
        const int cur = ks & 1;
        const bool has_next = (ks < EMBD / BK - 1);
        if (has_next) {
            const int k0 = (ks + 1) * BK;
            av0 = *(const float4*)(xrow + k0 + a_k);
            av1 = *(const float4*)(xrow + k0 + a_k + 4);
            bv0 = *(const float4*)(wptr + (long)k0 * EMBD);
            bv1 = *(const float4*)(wptr + (long)k0 * EMBD + 4);
        }
        GEMM_MICRO_DUP16(cur)
        if (has_next) {
            const int nxt = 1 - cur;
            As2[nxt][a_k + 0][a_row] = bcast2(av0.x);
            As2[nxt][a_k + 1][a_row] = bcast2(av0.y);
            As2[nxt][a_k + 2][a_row] = bcast2(av0.z);
            As2[nxt][a_k + 3][a_row] = bcast2(av0.w);
            As2[nxt][a_k + 4][a_row] = bcast2(av1.x);
            As2[nxt][a_k + 5][a_row] = bcast2(av1.y);
            As2[nxt][a_k + 6][a_row] = bcast2(av1.z);
            As2[nxt][a_k + 7][a_row] = bcast2(av1.w);
            *(float4*)&Bs[nxt][b_k][b_n]     = bv0;
            *(float4*)&Bs[nxt][b_k][b_n + 4] = bv1;
        }
        __syncthreads();
    }

    #pragma unroll
    for (int half = 0; half < 2; half++) {
        #pragma unroll
        for (int i = 0; i < 4; i++) {
            const int r = row0 + half * 64 + ty * 4 + i;
            if (r < nrows) {
                const int ai = half * 4 + i;
                float2 c0 = unpack2(acc2[ai][0]);
                float2 c1 = unpack2(acc2[ai][1]);
                float2 c2 = unpack2(acc2[ai][2]);
                float2 c3 = unpack2(acc2[ai][3]);
                float4 o0 = make_float4(c0.x, c0.y, c1.x, c1.y);
                float4 o1 = make_float4(c2.x, c2.y, c3.x, c3.y);
                *(float4*)(C + (long)r * EMBD + col0 + tx * 4)      = o0;
                *(float4*)(C + (long)r * EMBD + col0 + 64 + tx * 4) = o1;
            }
        }
    }
}

// =================== Wc projection (+bias), 64x128, dup-A, BK=16 ===========
#define WBM 64
__global__ void __launch_bounds__(256, 3)
wc_kernel(const float* __restrict__ X, const float* __restrict__ W,
          const float* __restrict__ bias, float* __restrict__ C)
{
    __shared__ ull   As2[2][BK][WBM];
    __shared__ float Bs [2][BK][BN];

    const int tid  = threadIdx.x;
    const int row0 = blockIdx.y * WBM;
    const int col0 = blockIdx.x * BN;

    const int a_row = tid >> 2;          // 0..63
    const int a_k   = (tid & 3) * 4;     // 0,4,8,12
    const int b_k   = tid >> 4;          // 0..15
    const int b_n   = (tid & 15) * 8;
    const int tx = tid & 15;
    const int ty = tid >> 4;

    const float* xrow = X + (long)(row0 + a_row) * EMBD;
    const float* wptr = W + (long)b_k * EMBD + col0 + b_n;

    float4 av, bv0, bv1;
    av  = *(const float4*)(xrow + a_k);
    bv0 = *(const float4*)(wptr);
    bv1 = *(const float4*)(wptr + 4);
    As2[0][a_k + 0][a_row] = bcast2(av.x);
    As2[0][a_k + 1][a_row] = bcast2(av.y);
    As2[0][a_k + 2][a_row] = bcast2(av.z);
    As2[0][a_k + 3][a_row] = bcast2(av.w);
    *(float4*)&Bs[0][b_k][b_n]     = bv0;
    *(float4*)&Bs[0][b_k][b_n + 4] = bv1;
    __syncthreads();

    ull acc2[4][4] = {};

    #pragma unroll 1
    for (int ks = 0; ks < EMBD / BK; ks++) {
        const int cur = ks & 1;
        const bool has_next = (ks < EMBD / BK - 1);
        if (has_next) {
            const int k0 = (ks + 1) * BK;
            av  = *(const float4*)(xrow + k0 + a_k);
            bv0 = *(const float4*)(wptr + (long)k0 * EMBD);
            bv1 = *(const float4*)(wptr + (long)k0 * EMBD + 4);
        }
        #pragma unroll
        for (int kk = 0; kk < BK; kk++) {
            ulonglong2 qa = *(const ulonglong2*)&As2[cur][kk][ty * 4];
            ulonglong2 qb = *(const ulonglong2*)&As2[cur][kk][ty * 4 + 2];
            ulonglong2 p0 = *(const ulonglong2*)&Bs[cur][kk][tx * 4];
            ulonglong2 p1 = *(const ulonglong2*)&Bs[cur][kk][64 + tx * 4];
            ull A2[4] = {qa.x, qa.y, qb.x, qb.y};
            ull B2[4] = {p0.x, p0.y, p1.x, p1.y};
            #pragma unroll
            for (int i = 0; i < 4; i++)
                #pragma unroll
                for (int j = 0; j < 4; j++)
                    acc2[i][j] = fma2(A2[i], B2[j], acc2[i][j]);
        }
        if (has_next) {
            const int nxt = 1 - cur;
            As2[nxt][a_k + 0][a_row] = bcast2(av.x);
            As2[nxt][a_k + 1][a_row] = bcast2(av.y);
            As2[nxt][a_k + 2][a_row] = bcast2(av.z);
            As2[nxt][a_k + 3][a_row] = bcast2(av.w);
            *(float4*)&Bs[nxt][b_k][b_n]     = bv0;
            *(float4*)&Bs[nxt][b_k][b_n + 4] = bv1;
        }
        __syncthreads();
    }

    float4 bb0 = *(const float4*)(bias + col0 + tx * 4);
    float4 bb1 = *(const float4*)(bias + col0 + 64 + tx * 4);

    #pragma unroll
    for (int i = 0; i < 4; i++) {
        const int r = row0 + ty * 4 + i;
        float2 c0 = unpack2(acc2[i][0]);
        float2 c1 = unpack2(acc2[i][1]);
        float2 c2 = unpack2(acc2[i][2]);
        float2 c3 = unpack2(acc2[i][3]);
        float4 o0 = make_float4(c0.x+bb0.x, c0.y+bb0.y, c1.x+bb0.z, c1.y+bb0.w);
        float4 o1 = make_float4(c2.x+bb1.x, c2.y+bb1.y, c3.x+bb1.z, c3.y+bb1.w);
        *(float4*)(C + (long)r * EMBD + col0 + tx * 4)      = o0;
        *(float4*)(C + (long)r * EMBD + col0 + 64 + tx * 4) = o1;
    }
}

// =================== attention: 2 queries/thread, 64-thread blocks =========
__global__ void __launch_bounds__(64)
attn_kernel(const float* __restrict__ Q, const float* __restrict__ K,
            const float* __restrict__ V, float* __restrict__ O)
{
    __shared__ float Ks[128][DHEAD];
    __shared__ float Vs[128][DHEAD];

    const int h = blockIdx.x;
    const int b = blockIdx.y;
    const int tid = threadIdx.x;      // 0..63
    const int ma = tid;
    const int mb = tid + 64;

    ull qa[8], qb[8];
    {
        const float* qpa = Q + ((long)b * MROWS + ma) * EMBD + h * DHEAD;
        const float* qpb = Q + ((long)b * MROWS + mb) * EMBD + h * DHEAD;
        #pragma unroll
        for (int p = 0; p < 4; p++) {
            ulonglong2 va = *(const ulonglong2*)(qpa + p * 4);
            ulonglong2 vb = *(const ulonglong2*)(qpb + p * 4);
            qa[2*p] = va.x; qa[2*p+1] = va.y;
            qb[2*p] = vb.x; qb[2*p+1] = vb.y;
        }
    }

    float la = 0.0f, lb = 0.0f;
    ull acca[8] = {}, accb[8] = {};

    #pragma unroll 1
    for (int c = 0; c < 4; c++) {
        const int t0 = c * 128;
        __syncthreads();
        #pragma unroll
        for (int j = 0; j < 8; j++) {
            const int idx = tid + j * 64;          // 0..511
            const int rr = idx >> 2, cc = (idx & 3) * 4;
            const long base = ((long)b * TTOK + t0 + rr) * EMBD + h * DHEAD + cc;
            *(float4*)&Ks[rr][cc] = *(const float4*)(K + base);
            *(float4*)&Vs[rr][cc] = *(const float4*)(V + base);
        }
        __syncthreads();

        #pragma unroll 1
        for (int tt = 0; tt < 128; tt += 4) {
            float sa[4], sb[4];
            #pragma unroll
            for (int j = 0; j < 4; j++) {
                const ulonglong2* kp = (const ulonglong2*)Ks[tt + j];
                ulonglong2 k0 = kp[0], k1 = kp[1], k2v = kp[2], k3 = kp[3];
                ull da = mul2(qa[0], k0.x);
                ull db = mul2(qb[0], k0.x);
                da = fma2(qa[1], k0.y, da);  db = fma2(qb[1], k0.y, db);
                da = fma2(qa[2], k1.x, da);  db = fma2(qb[2], k1.x, db);
                da = fma2(qa[3], k1.y, da);  db = fma2(qb[3], k1.y, db);
                da = fma2(qa[4], k2v.x, da); db = fma2(qb[4], k2v.x, db);
                da = fma2(qa[5], k2v.y, da); db = fma2(qb[5], k2v.y, db);
                da = fma2(qa[6], k3.x, da);  db = fma2(qb[6], k3.x, db);
                da = fma2(qa[7], k3.y, da);  db = fma2(qb[7], k3.y, db);
                float2 fa = unpack2(da), fb = unpack2(db);
                sa[j] = (fa.x + fa.y) * 0.25f;
                sb[j] = (fb.x + fb.y) * 0.25f;
            }
            float pa[4], pb[4];
            #pragma unroll
            for (int j = 0; j < 4; j++) {
                pa[j] = __expf(sa[j]); la += pa[j];
                pb[j] = __expf(sb[j]); lb += pb[j];
            }
            #pragma unroll
            for (int j = 0; j < 4; j++) {
                const ull pba = bcast2(pa[j]);
                const ull pbb = bcast2(pb[j]);
                const ulonglong2* vp = (const ulonglong2*)Vs[tt + j];
                ulonglong2 v0 = vp[0], v1 = vp[1];
                acca[0] = fma2(pba, v0.x, acca[0]); accb[0] = fma2(pbb, v0.x, accb[0]);
                acca[1] = fma2(pba, v0.y, acca[1]); accb[1] = fma2(pbb, v0.y, accb[1]);
                acca[2] = fma2(pba, v1.x, acca[2]); accb[2] = fma2(pbb, v1.x, accb[2]);
                acca[3] = fma2(pba, v1.y, acca[3]); accb[3] = fma2(pbb, v1.y, accb[3]);
                ulonglong2 v2v = vp[2], v3 = vp[3];
                acca[4] = fma2(pba, v2v.x, acca[4]); accb[4] = fma2(pbb, v2v.x, accb[4]);
                acca[5] = fma2(pba, v2v.y, acca[5]); accb[5] = fma2(pbb, v2v.y, accb[5]);
                acca[6] = fma2(pba, v3.x, acca[6]);  accb[6] = fma2(pbb, v3.x, accb[6]);
                acca[7] = fma2(pba, v3.y, acca[7]);  accb[7] = fma2(pbb, v3.y, accb[7]);
            }
        }
    }

    // tail token t = 512 (from global)
    {
        const long base = ((long)b * TTOK + 512) * EMBD + h * DHEAD;
        const ulonglong2* kp = (const ulonglong2*)(K + base);
        ulonglong2 k0 = kp[0], k1 = kp[1], k2v = kp[2], k3 = kp[3];
        ull da = mul2(qa[0], k0.x);
        ull db = mul2(qb[0], k0.x);
        da = fma2(qa[1], k0.y, da);  db = fma2(qb[1], k0.y, db);
        da = fma2(qa[2], k1.x, da);  db = fma2(qb[2], k1.x, db);
        da = fma2(qa[3], k1.y, da);  db = fma2(qb[3], k1.y, db);
        da = fma2(qa[4], k2v.x, da); db = fma2(qb[4], k2v.x, db);
        da = fma2(qa[5], k2v.y, da); db = fma2(qb[5], k2v.y, db);
        da = fma2(qa[6], k3.x, da);  db = fma2(qb[6], k3.x, db);
        da = fma2(qa[7], k3.y, da);  db = fma2(qb[7], k3.y, db);
        float2 fa = unpack2(da), fb = unpack2(db);
        const float pa = __expf((fa.x + fa.y) * 0.25f);
        const float pb = __expf((fb.x + fb.y) * 0.25f);
        la += pa; lb += pb;
        const ull pba = bcast2(pa);
        const ull pbb = bcast2(pb);
        const ulonglong2* vp = (const ulonglong2*)(V + base);
        ulonglong2 v0 = vp[0], v1 = vp[1], v2v = vp[2], v3 = vp[3];
        acca[0] = fma2(pba, v0.x,  acca[0]); accb[0] = fma2(pbb, v0.x,  accb[0]);
        acca[1] = fma2(pba, v0.y,  acca[1]); accb[1] = fma2(pbb, v0.y,  accb[1]);
        acca[2] = fma2(pba, v1.x,  acca[2]); accb[2] = fma2(pbb, v1.x,  accb[2]);
        acca[3] = fma2(pba, v1.y,  acca[3]); accb[3] = fma2(pbb, v1.y,  accb[3]);
        acca[4] = fma2(pba, v2v.x, acca[4]); accb[4] = fma2(pbb, v2v.x, accb[4]);
        acca[5] = fma2(pba, v2v.y, acca[5]); accb[5] = fma2(pbb, v2v.y, accb[5]);
        acca[6] = fma2(pba, v3.x,  acca[6]); accb[6] = fma2(pbb, v3.x,  accb[6]);
        acca[7] = fma2(pba, v3.y,  acca[7]); accb[7] = fma2(pbb, v3.y,  accb[7]);
    }

    const float inva = 1.0f / la;
    const float invb = 1.0f / lb;
    float* opa = O + ((long)b * MROWS + ma) * EMBD + h * DHEAD;
    float* opb = O + ((long)b * MROWS + mb) * EMBD + h * DHEAD;
    #pragma unroll
    for (int p = 0; p < 4; p++) {
        float2 x0 = unpack2(acca[2*p]);
        float2 x1 = unpack2(acca[2*p+1]);
        *(float4*)(opa + p * 4) = make_float4(x0.x*inva, x0.y*inva, x1.x*inva, x1.y*inva);
        float2 y0 = unpack2(accb[2*p]);
        float2 y1 = unpack2(accb[2*p+1]);
        *(float4*)(opb + p * 4) = make_float4(y0.x*invb, y0.y*invb, y1.x*invb, y1.y*invb);
    }
}

// =================== score2: 128x128, dup-A BK=16, scalar epilogue =========
// out/mask rows have stride 513 (odd) -> epilogue must use scalar accesses.
__global__ void __launch_bounds__(256, 2)
score2_kernel(const float* __restrict__ MH, const float* __restrict__ jobs,
              const float* __restrict__ skip, const float* __restrict__ mask,
              float* __restrict__ out, float* __restrict__ sums)
{
    __shared__ ull   As2[2][BK][BM];
    __shared__ float Bs [2][BK][BN + 4];
    __shared__ float red[256];

    const int tid  = threadIdx.x;
    const int b    = blockIdx.z;
    const int col0 = blockIdx.x * BN;   // 0,128,256,384 -> t <= 511 always

    const int a_row = tid >> 1;         // 0..127
    const int a_k   = (tid & 1) * 8;    // 0 or 8
    const int tx = tid & 15;
    const int ty = tid >> 4;

    const float* arow = MH + ((long)b * MROWS + a_row) * EMBD;

    const int t_l = tid >> 1;           // 0..127
    const int b_k = (tid & 1) * 8;      // 0 or 8
    const float* brow = jobs_row(jobs, skip, b, col0 + t_l);

    float4 av0, av1, bv0, bv1;
    av0 = *(const float4*)(arow + a_k);
    av1 = *(const float4*)(arow + a_k + 4);
    bv0 = *(const float4*)(brow + b_k);
    bv1 = *(const float4*)(brow + b_k + 4);
    As2[0][a_k + 0][a_row] = bcast2(av0.x);
    As2[0][a_k + 1][a_row] = bcast2(av0.y);
    As2[0][a_k + 2][a_row] = bcast2(av0.z);
    As2[0][a_k + 3][a_row] = bcast2(av0.w);
    As2[0][a_k + 4][a_row] = bcast2(av1.x);
    As2[0][a_k + 5][a_row] = bcast2(av1.y);
    As2[0][a_k + 6][a_row] = bcast2(av1.z);
    As2[0][a_k + 7][a_row] = bcast2(av1.w);
    Bs[0][b_k+0][t_l]=bv0.x; Bs[0][b_k+1][t_l]=bv0.y;
    Bs[0][b_k+2][t_l]=bv0.z; Bs[0][b_k+3][t_l]=bv0.w;
    Bs[0][b_k+4][t_l]=bv1.x; Bs[0][b_k+5][t_l]=bv1.y;
    Bs[0][b_k+6][t_l]=bv1.z; Bs[0][b_k+7][t_l]=bv1.w;
    __syncthreads();

    ull acc2[8][4] = {};

    #pragma unroll 1
    for (int ks = 0; ks < EMBD / BK; ks++) {
        const int cur = ks & 1;
        const bool has_next = (ks < EMBD / BK - 1);
        if (has_next) {
            const int k0 = (ks + 1) * BK;
            av0 = *(const float4*)(arow + k0 + a_k);
            av1 = *(const float4*)(arow + k0 + a_k + 4);
            bv0 = *(const float4*)(brow + k0 + b_k);
            bv1 = *(const float4*)(brow + k0 + b_k + 4);
        }
        GEMM_MICRO_DUP16(cur)
        if (has_next) {
            const int nxt = 1 - cur;
            As2[nxt][a_k + 0][a_row] = bcast2(av0.x);
            As2[nxt][a_k + 1][a_row] = bcast2(av0.y);
            As2[nxt][a_k + 2][a_row] = bcast2(av0.z);
            As2[nxt][a_k + 3][a_row] = bcast2(av0.w);
            As2[nxt][a_k + 4][a_row] = bcast2(av1.x);
            As2[nxt][a_k + 5][a_row] = bcast2(av1.y);
            As2[nxt][a_k + 6][a_row] = bcast2(av1.z);
            As2[nxt][a_k + 7][a_row] = bcast2(av1.w);
            Bs[nxt][b_k+0][t_l]=bv0.x; Bs[nxt][b_k+1][t_l]=bv0.y;
            Bs[nxt][b_k+2][t_l]=bv0.z; Bs[nxt][b_k+3][t_l]=bv0.w;
            Bs[nxt][b_k+4][t_l]=bv1.x; Bs[nxt][b_k+5][t_l]=bv1.y;
            Bs[nxt][b_k+6][t_l]=bv1.z; Bs[nxt][b_k+7][t_l]=bv1.w;
        }
        __syncthreads();
    }

    float lsum = 0.0f;
    #pragma unroll
    for (int half = 0; half < 2; half++) {
        #pragma unroll
        for (int i = 0; i < 4; i++) {
            const int m = half * 64 + ty * 4 + i;
            const int ai = half * 4 + i;
            const long rowbase = (long)b * OUT_PER_B + (long)m * TTOK;
            #pragma unroll
            for (int jh = 0; jh < 2; jh++) {
                const int t = col0 + jh * 64 + tx * 4;
                float2 v0 = unpack2(acc2[ai][jh * 2 + 0]);
                float2 v1 = unpack2(acc2[ai][jh * 2 + 1]);
                float vv[4] = {v0.x, v0.y, v1.x, v1.y};
                #pragma unroll
                for (int e = 0; e < 4; e++) {
                    const long li = rowbase + t + e;
                    const float y = __expf(10.0f * tanh_fast(vv[e] * 0.0625f) + mask[li]);
                    out[li] = y;
                    lsum += y;
                }
            }
        }
    }

    red[tid] = lsum;
    __syncthreads();
    #pragma unroll
    for (int s = 128; s > 0; s >>= 1) {
        if (tid < s) red[tid] += red[tid + s];
        __syncthreads();
    }
    if (tid == 0) atomicAdd(&sums[b], red[0]);
}

// =================== t=512 column tail: 64 blocks x 128 thr ================
__global__ void __launch_bounds__(128)
tail_kernel(const float* __restrict__ MH, const float* __restrict__ jobs,
            const float* __restrict__ mask, float* __restrict__ out,
            float* __restrict__ sums)
{
    __shared__ float jrow[EMBD];
    __shared__ float red[128];

    const int b = blockIdx.x;
    const int m = threadIdx.x;

    const float* jr = jobs + ((long)b * JJOBS + 511) * EMBD;
    *(float2*)&jrow[m * 2] = *(const float2*)(jr + m * 2);
    __syncthreads();

    const float* mh = MH + ((long)b * MROWS + m) * EMBD;
    ull d2 = bcast2(0.0f);
    #pragma unroll
    for (int k = 0; k < EMBD; k += 8) {
        ulonglong2 a = *(const ulonglong2*)(mh + k);
        ulonglong2 a2 = *(const ulonglong2*)(mh + k + 4);
        ulonglong2 w = *(const ulonglong2*)&jrow[k];
        ulonglong2 w2 = *(const ulonglong2*)&jrow[k + 4];
        d2 = fma2(a.x, w.x, d2);
        d2 = fma2(a.y, w.y, d2);
        d2 = fma2(a2.x, w2.x, d2);
        d2 = fma2(a2.y, w2.y, d2);
    }
    float2 f = unpack2(d2);
    const float sc = (f.x + f.y) * 0.0625f;
    const long li = (long)b * OUT_PER_B + (long)m * TTOK + 512;
    const float y = __expf(10.0f * tanh_fast(sc) + mask[li]);
    out[li] = y;

    red[m] = y;
    __syncthreads();
    #pragma unroll
    for (int s = 64; s > 0; s >>= 1) {
        if (m < s) red[m] += red[m + s];
        __syncthreads();
    }
    if (m == 0) atomicAdd(&sums[b], red[0]);
}

// =================== normalize =======================
__global__ void __launch_bounds__(256)
norm_kernel(float4* __restrict__ out, const float* __restrict__ sums)
{
    const int b = blockIdx.y;
    const long per_b4 = OUT_PER_B / 4;
    const long idx = (long)blockIdx.x * blockDim.x + threadIdx.x;
    if (idx < per_b4) {
        const float inv = 1.0f / sums[b];
        float4 v = out[(long)b * per_b4 + idx];
        v.x *= inv; v.y *= inv; v.z *= inv; v.w *= inv;
        out[(long)b * per_b4 + idx] = v;
    }
}

// =================== launch ===================
extern "C" void kernel_launch(void* const* d_in, const int* in_sizes, int n_in,
                              void* d_out, int out_size)
{
    const float* machine = (const float*)d_in[0];
    const float* jobs    = (const float*)d_in[1];
    const float* mask    = (const float*)d_in[2];
    const float* Wq3     = (const float*)d_in[3];
    const float* Wk      = (const float*)d_in[4];
    const float* Wv      = (const float*)d_in[5];
    const float* Wc      = (const float*)d_in[6];
    const float* bc      = (const float*)d_in[7];
    const float* skip    = (const float*)d_in[8];
    float* out = (float*)d_out;

    float *Qp, *Kp, *Vp, *Op, *MHp, *Sp;
    cudaGetSymbolAddress((void**)&Qp,  g_Q);
    cudaGetSymbolAddress((void**)&Kp,  g_K);
    cudaGetSymbolAddress((void**)&Vp,  g_V);
    cudaGetSymbolAddress((void**)&Op,  g_O);
    cudaGetSymbolAddress((void**)&MHp, g_MH);
    cudaGetSymbolAddress((void**)&Sp,  g_SUM);

    const int kv_tiles = (BATCH * TTOK + BM - 1) / BM;   // 257
    proj_kernel<<<dim3(EMBD / BN, kv_tiles, 3), 256>>>(
        jobs, skip, machine, Wk, Wv, Wq3, Kp, Vp, Qp, Sp);

    attn_kernel<<<dim3(HEADS, BATCH), 64>>>(Qp, Kp, Vp, Op);

    wc_kernel<<<dim3(EMBD / BN, (BATCH * MROWS) / WBM), 256>>>(Op, Wc, bc, MHp);

    score2_kernel<<<dim3(4, 1, BATCH), 256>>>(MHp, jobs, skip, mask, out, Sp);
    tail_kernel<<<BATCH, 128>>>(MHp, jobs, mask, out, Sp);

    const int per_b4 = OUT_PER_B / 4;
    norm_kernel<<<dim3((per_b4 + 255) / 256, BATCH), 256>>>((float4*)out, Sp);
}

// round 11
// speedup vs baseline: 1.1425x; 1.1425x over previous
#include <cuda_runtime.h>
#include <cuda_bf16.h>
#include <math.h>

#define EMBD   256
#define HEADS  16
#define DHEAD  16
#define BATCH  64
#define MROWS  128
#define JJOBS  512
#define TTOK   513
#define OUT_PER_B (MROWS * TTOK)   // 65664

typedef unsigned long long ull;

__device__ float g_Q [BATCH * MROWS * EMBD];
__device__ float g_K [BATCH * TTOK  * EMBD];
__device__ float g_V [BATCH * TTOK  * EMBD];
__device__ float g_O [BATCH * MROWS * EMBD];
__device__ float g_MH[BATCH * MROWS * EMBD];
__device__ float g_SUM[BATCH];

// ---------------- packed f32x2 helpers (sm_103a) ----------------
__device__ __forceinline__ ull fma2(ull a, ull b, ull c) {
    ull d; asm("fma.rn.f32x2 %0, %1, %2, %3;" : "=l"(d) : "l"(a), "l"(b), "l"(c));
    return d;
}
__device__ __forceinline__ ull mul2(ull a, ull b) {
    ull d; asm("mul.rn.f32x2 %0, %1, %2;" : "=l"(d) : "l"(a), "l"(b));
    return d;
}
__device__ __forceinline__ ull bcast2(float x) {
    ull d; asm("mov.b64 %0, {%1, %2};" : "=l"(d) : "f"(x), "f"(x));
    return d;
}
__device__ __forceinline__ float2 unpack2(ull v) {
    float2 f; asm("mov.b64 {%0, %1}, %2;" : "=f"(f.x), "=f"(f.y) : "l"(v));
    return f;
}

// exact-enough tanh: (1 - 2/(e^{2x}+1)); err ~1e-6
__device__ __forceinline__ float tanh_fast(float x) {
    const float e = __expf(2.0f * x);
    return 1.0f - __fdividef(2.0f, e + 1.0f);
}

__device__ __forceinline__ const float* jobs_row(const float* __restrict__ jobs,
                                                 const float* __restrict__ skip,
                                                 int b, int t) {
    return (t == 0) ? skip : jobs + ((long)b * JJOBS + (t - 1)) * EMBD;
}

// =================== tiles ===================
#define BM 128
#define BN 128
#define BK 16
#define ASTRIDE (BM + 4)

#define GEMM_MICRO(cur)                                                        \
    _Pragma("unroll")                                                          \
    for (int kk = 0; kk < BK; kk++) {                                          \
        float4 a0 = *(const float4*)&As[cur][kk][ty * 4];                      \
        float4 a1 = *(const float4*)&As[cur][kk][64 + ty * 4];                 \
        ulonglong2 p0 = *(const ulonglong2*)&Bs[cur][kk][tx * 4];              \
        ulonglong2 p1 = *(const ulonglong2*)&Bs[cur][kk][64 + tx * 4];         \
        ull B2[4] = {p0.x, p0.y, p1.x, p1.y};                                  \
        float a[8] = {a0.x,a0.y,a0.z,a0.w,a1.x,a1.y,a1.z,a1.w};                \
        _Pragma("unroll")                                                      \
        for (int i = 0; i < 8; i++) {                                          \
            const ull ai = bcast2(a[i]);                                       \
            _Pragma("unroll")                                                  \
            for (int j = 0; j < 4; j++)                                        \
                acc2[i][j] = fma2(ai, B2[j], acc2[i][j]);                      \
        }                                                                      \
    }

// =================== merged projection kernel (Q, K, V) ====================
__global__ void __launch_bounds__(256, 2)
proj_kernel(const float* __restrict__ jobs, const float* __restrict__ skip,
            const float* __restrict__ machine,
            const float* __restrict__ Wk, const float* __restrict__ Wv,
            const float* __restrict__ Wq,
            float* __restrict__ Kout, float* __restrict__ Vout,
            float* __restrict__ Qout, float* __restrict__ sums)
{
    __shared__ float As[2][BK][ASTRIDE];
    __shared__ float Bs[2][BK][BN];

    const int z = blockIdx.z;
    const int row0 = blockIdx.y * BM;
    const int nrows = (z == 2) ? (BATCH * MROWS) : (BATCH * TTOK);

    if (z == 2 && blockIdx.x == 0 && blockIdx.y == 0 && threadIdx.x < BATCH)
        sums[threadIdx.x] = 0.0f;
    if (row0 >= nrows) return;

    const float* W = (z == 0) ? Wk : (z == 1) ? Wv : Wq;
    float*       C = (z == 0) ? Kout : (z == 1) ? Vout : Qout;

    const int tid  = threadIdx.x;
    const int col0 = blockIdx.x * BN;

    const int a_row = tid >> 1;
    const int a_k   = (tid & 1) * 8;
    const int b_k   = tid >> 4;
    const int b_n   = (tid & 15) * 8;
    const int tx = tid & 15;
    const int ty = tid >> 4;

    const float* xrow;
    {
        int grow = row0 + a_row;
        if (grow > nrows - 1) grow = nrows - 1;
        if (z == 2) {
            xrow = machine + (long)grow * EMBD;
        } else {
            const int b = grow / TTOK;
            const int t = grow - b * TTOK;
            xrow = jobs_row(jobs, skip, b, t);
        }
    }
    const float* wptr = W + (long)b_k * EMBD + col0 + b_n;

    float4 av0, av1, bv0, bv1;
    av0 = *(const float4*)(xrow + a_k);
    av1 = *(const float4*)(xrow + a_k + 4);
    bv0 = *(const float4*)(wptr);
    bv1 = *(const float4*)(wptr + 4);
    As[0][a_k+0][a_row]=av0.x; As[0][a_k+1][a_row]=av0.y;
    As[0][a_k+2][a_row]=av0.z; As[0][a_k+3][a_row]=av0.w;
    As[0][a_k+4][a_row]=av1.x; As[0][a_k+5][a_row]=av1.y;
    As[0][a_k+6][a_row]=av1.z; As[0][a_k+7][a_row]=av1.w;
    *(float4*)&Bs[0][b_k][b_n]     = bv0;
    *(float4*)&Bs[0][b_k][b_n + 4] = bv1;
    __syncthreads();

    ull acc2[8][4] = {};

    #pragma unroll 1
    for (int ks = 0; ks < EMBD / BK; ks++) {
        const int cur = ks & 1;
        const bool has_next = (ks < EMBD / BK - 1);
        if (has_next) {
            const int k0 = (ks + 1) * BK;
            av0 = *(const float4*)(xrow + k0 + a_k);
            av1 = *(const float4*)(xrow + k0 + a_k + 4);
            bv0 = *(const float4*)(wptr + (long)k0 * EMBD);
            bv1 = *(const float4*)(wptr + (long)k0 * EMBD + 4);
        }
        GEMM_MICRO(cur)
        if (has_next) {
            const int nxt = 1 - cur;
            As[nxt][a_k+0][a_row]=av0.x; As[nxt][a_k+1][a_row]=av0.y;
            As[nxt][a_k+2][a_row]=av0.z; As[nxt][a_k+3][a_row]=av0.w;
            As[nxt][a_k+4][a_row]=av1.x; As[nxt][a_k+5][a_row]=av1.y;
            As[nxt][a_k+6][a_row]=av1.z; As[nxt][a_k+7][a_row]=av1.w;
            *(float4*)&Bs[nxt][b_k][b_n]     = bv0;
            *(float4*)&Bs[nxt][b_k][b_n + 4] = bv1;
        }
        __syncthreads();
    }

    #pragma unroll
    for (int half = 0; half < 2; half++) {
        #pragma unroll
        for (int i = 0; i < 4; i++) {
            const int r = row0 + half * 64 + ty * 4 + i;
            if (r < nrows) {
                const int ai = half * 4 + i;
                float2 c0 = unpack2(acc2[ai][0]);
                float2 c1 = unpack2(acc2[ai][1]);
                float2 c2 = unpack2(acc2[ai][2]);
                float2 c3 = unpack2(acc2[ai][3]);
                float4 o0 = make_float4(c0.x, c0.y, c1.x, c1.y);
                float4 o1 = make_float4(c2.x, c2.y, c3.x, c3.y);
                *(float4*)(C + (long)r * EMBD + col0 + tx * 4)      = o0;
                *(float4*)(C + (long)r * EMBD + col0 + 64 + tx * 4) = o1;
            }
        }
    }
}

// =================== Wc projection (+bias), 64x128 tiles ====================
#define WBM 64
__global__ void __launch_bounds__(256)
wc_kernel(const float* __restrict__ X, const float* __restrict__ W,
          const float* __restrict__ bias, float* __restrict__ C)
{
    __shared__ float As[2][BK][WBM + 4];
    __shared__ float Bs[2][BK][BN];

    const int tid  = threadIdx.x;
    const int row0 = blockIdx.y * WBM;
    const int col0 = blockIdx.x * BN;

    const int a_row = tid >> 2;
    const int a_k   = (tid & 3) * 4;
    const int b_k   = tid >> 4;
    const int b_n   = (tid & 15) * 8;
    const int tx = tid & 15;
    const int ty = tid >> 4;

    const float* xrow = X + (long)(row0 + a_row) * EMBD;
    const float* wptr = W + (long)b_k * EMBD + col0 + b_n;

    float4 av, bv0, bv1;
    av  = *(const float4*)(xrow + a_k);
    bv0 = *(const float4*)(wptr);
    bv1 = *(const float4*)(wptr + 4);
    As[0][a_k+0][a_row]=av.x; As[0][a_k+1][a_row]=av.y;
    As[0][a_k+2][a_row]=av.z; As[0][a_k+3][a_row]=av.w;
    *(float4*)&Bs[0][b_k][b_n]     = bv0;
    *(float4*)&Bs[0][b_k][b_n + 4] = bv1;
    __syncthreads();

    ull acc2[4][4] = {};

    #pragma unroll 1
    for (int ks = 0; ks < EMBD / BK; ks++) {
        const int cur = ks & 1;
        const bool has_next = (ks < EMBD / BK - 1);
        if (has_next) {
            const int k0 = (ks + 1) * BK;
            av  = *(const float4*)(xrow + k0 + a_k);
            bv0 = *(const float4*)(wptr + (long)k0 * EMBD);
            bv1 = *(const float4*)(wptr + (long)k0 * EMBD + 4);
        }
        #pragma unroll
        for (int kk = 0; kk < BK; kk++) {
            float4 a0 = *(const float4*)&As[cur][kk][ty * 4];
            ulonglong2 p0 = *(const ulonglong2*)&Bs[cur][kk][tx * 4];
            ulonglong2 p1 = *(const ulonglong2*)&Bs[cur][kk][64 + tx * 4];
            ull B2[4] = {p0.x, p0.y, p1.x, p1.y};
            float a[4] = {a0.x, a0.y, a0.z, a0.w};
            #pragma unroll
            for (int i = 0; i < 4; i++) {
                const ull ai = bcast2(a[i]);
                #pragma unroll
                for (int j = 0; j < 4; j++)
                    acc2[i][j] = fma2(ai, B2[j], acc2[i][j]);
            }
        }
        if (has_next) {
            const int nxt = 1 - cur;
            As[nxt][a_k+0][a_row]=av.x; As[nxt][a_k+1][a_row]=av.y;
            As[nxt][a_k+2][a_row]=av.z; As[nxt][a_k+3][a_row]=av.w;
            *(float4*)&Bs[nxt][b_k][b_n]     = bv0;
            *(float4*)&Bs[nxt][b_k][b_n + 4] = bv1;
        }
        __syncthreads();
    }

    float4 bb0 = *(const float4*)(bias + col0 + tx * 4);
    float4 bb1 = *(const float4*)(bias + col0 + 64 + tx * 4);

    #pragma unroll
    for (int i = 0; i < 4; i++) {
        const int r = row0 + ty * 4 + i;
        float2 c0 = unpack2(acc2[i][0]);
        float2 c1 = unpack2(acc2[i][1]);
        float2 c2 = unpack2(acc2[i][2]);
        float2 c3 = unpack2(acc2[i][3]);
        float4 o0 = make_float4(c0.x+bb0.x, c0.y+bb0.y, c1.x+bb0.z, c1.y+bb0.w);
        float4 o1 = make_float4(c2.x+bb1.x, c2.y+bb1.y, c3.x+bb1.z, c3.y+bb1.w);
        *(float4*)(C + (long)r * EMBD + col0 + tx * 4)      = o0;
        *(float4*)(C + (long)r * EMBD + col0 + 64 + tx * 4) = o1;
    }
}

// =================== attention: 2 queries/thread, 64-thread blocks =========
__global__ void __launch_bounds__(64)
attn_kernel(const float* __restrict__ Q, const float* __restrict__ K,
            const float* __restrict__ V, float* __restrict__ O)
{
    __shared__ float Ks[128][DHEAD];
    __shared__ float Vs[128][DHEAD];

    const int h = blockIdx.x;
    const int b = blockIdx.y;
    const int tid = threadIdx.x;      // 0..63
    const int ma = tid;
    const int mb = tid + 64;

    ull qa[8], qb[8];
    {
        const float* qpa = Q + ((long)b * MROWS + ma) * EMBD + h * DHEAD;
        const float* qpb = Q + ((long)b * MROWS + mb) * EMBD + h * DHEAD;
        #pragma unroll
        for (int p = 0; p < 4; p++) {
            ulonglong2 va = *(const ulonglong2*)(qpa + p * 4);
            ulonglong2 vb = *(const ulonglong2*)(qpb + p * 4);
            qa[2*p] = va.x; qa[2*p+1] = va.y;
            qb[2*p] = vb.x; qb[2*p+1] = vb.y;
        }
    }

    float la = 0.0f, lb = 0.0f;
    ull acca[8] = {}, accb[8] = {};

    #pragma unroll 1
    for (int c = 0; c < 4; c++) {
        const int t0 = c * 128;
        __syncthreads();
        #pragma unroll
        for (int j = 0; j < 8; j++) {
            const int idx = tid + j * 64;          // 0..511
            const int rr = idx >> 2, cc = (idx & 3) * 4;
            const long base = ((long)b * TTOK + t0 + rr) * EMBD + h * DHEAD + cc;
            *(float4*)&Ks[rr][cc] = *(const float4*)(K + base);
            *(float4*)&Vs[rr][cc] = *(const float4*)(V + base);
        }
        __syncthreads();

        #pragma unroll 1
        for (int tt = 0; tt < 128; tt += 4) {
            float sa[4], sb[4];
            #pragma unroll
            for (int j = 0; j < 4; j++) {
                const ulonglong2* kp = (const ulonglong2*)Ks[tt + j];
                ulonglong2 k0 = kp[0], k1 = kp[1], k2v = kp[2], k3 = kp[3];
                ull da = mul2(qa[0], k0.x);
                ull db = mul2(qb[0], k0.x);
                da = fma2(qa[1], k0.y, da);  db = fma2(qb[1], k0.y, db);
                da = fma2(qa[2], k1.x, da);  db = fma2(qb[2], k1.x, db);
                da = fma2(qa[3], k1.y, da);  db = fma2(qb[3], k1.y, db);
                da = fma2(qa[4], k2v.x, da); db = fma2(qb[4], k2v.x, db);
                da = fma2(qa[5], k2v.y, da); db = fma2(qb[5], k2v.y, db);
                da = fma2(qa[6], k3.x, da);  db = fma2(qb[6], k3.x, db);
                da = fma2(qa[7], k3.y, da);  db = fma2(qb[7], k3.y, db);
                float2 fa = unpack2(da), fb = unpack2(db);
                sa[j] = (fa.x + fa.y) * 0.25f;
                sb[j] = (fb.x + fb.y) * 0.25f;
            }
            float pa[4], pb[4];
            #pragma unroll
            for (int j = 0; j < 4; j++) {
                pa[j] = __expf(sa[j]); la += pa[j];
                pb[j] = __expf(sb[j]); lb += pb[j];
            }
            #pragma unroll
            for (int j = 0; j < 4; j++) {
                const ull pba = bcast2(pa[j]);
                const ull pbb = bcast2(pb[j]);
                const ulonglong2* vp = (const ulonglong2*)Vs[tt + j];
                ulonglong2 v0 = vp[0], v1 = vp[1];
                acca[0] = fma2(pba, v0.x, acca[0]); accb[0] = fma2(pbb, v0.x, accb[0]);
                acca[1] = fma2(pba, v0.y, acca[1]); accb[1] = fma2(pbb, v0.y, accb[1]);
                acca[2] = fma2(pba, v1.x, acca[2]); accb[2] = fma2(pbb, v1.x, accb[2]);
                acca[3] = fma2(pba, v1.y, acca[3]); accb[3] = fma2(pbb, v1.y, accb[3]);
                ulonglong2 v2v = vp[2], v3 = vp[3];
                acca[4] = fma2(pba, v2v.x, acca[4]); accb[4] = fma2(pbb, v2v.x, accb[4]);
                acca[5] = fma2(pba, v2v.y, acca[5]); accb[5] = fma2(pbb, v2v.y, accb[5]);
                acca[6] = fma2(pba, v3.x, acca[6]);  accb[6] = fma2(pbb, v3.x, accb[6]);
                acca[7] = fma2(pba, v3.y, acca[7]);  accb[7] = fma2(pbb, v3.y, accb[7]);
            }
        }
    }

    // tail token t = 512 (from global)
    {
        const long base = ((long)b * TTOK + 512) * EMBD + h * DHEAD;
        const ulonglong2* kp = (const ulonglong2*)(K + base);
        ulonglong2 k0 = kp[0], k1 = kp[1], k2v = kp[2], k3 = kp[3];
        ull da = mul2(qa[0], k0.x);
        ull db = mul2(qb[0], k0.x);
        da = fma2(qa[1], k0.y, da);  db = fma2(qb[1], k0.y, db);
        da = fma2(qa[2], k1.x, da);  db = fma2(qb[2], k1.x, db);
        da = fma2(qa[3], k1.y, da);  db = fma2(qb[3], k1.y, db);
        da = fma2(qa[4], k2v.x, da); db = fma2(qb[4], k2v.x, db);
        da = fma2(qa[5], k2v.y, da); db = fma2(qb[5], k2v.y, db);
        da = fma2(qa[6], k3.x, da);  db = fma2(qb[6], k3.x, db);
        da = fma2(qa[7], k3.y, da);  db = fma2(qb[7], k3.y, db);
        float2 fa = unpack2(da), fb = unpack2(db);
        const float pa = __expf((fa.x + fa.y) * 0.25f);
        const float pb = __expf((fb.x + fb.y) * 0.25f);
        la += pa; lb += pb;
        const ull pba = bcast2(pa);
        const ull pbb = bcast2(pb);
        const ulonglong2* vp = (const ulonglong2*)(V + base);
        ulonglong2 v0 = vp[0], v1 = vp[1], v2v = vp[2], v3 = vp[3];
        acca[0] = fma2(pba, v0.x,  acca[0]); accb[0] = fma2(pbb, v0.x,  accb[0]);
        acca[1] = fma2(pba, v0.y,  acca[1]); accb[1] = fma2(pbb, v0.y,  accb[1]);
        acca[2] = fma2(pba, v1.x,  acca[2]); accb[2] = fma2(pbb, v1.x,  accb[2]);
        acca[3] = fma2(pba, v1.y,  acca[3]); accb[3] = fma2(pbb, v1.y,  accb[3]);
        acca[4] = fma2(pba, v2v.x, acca[4]); accb[4] = fma2(pbb, v2v.x, accb[4]);
        acca[5] = fma2(pba, v2v.y, acca[5]); accb[5] = fma2(pbb, v2v.y, accb[5]);
        acca[6] = fma2(pba, v3.x,  acca[6]); accb[6] = fma2(pbb, v3.x,  accb[6]);
        acca[7] = fma2(pba, v3.y,  acca[7]); accb[7] = fma2(pbb, v3.y,  accb[7]);
    }

    const float inva = 1.0f / la;
    const float invb = 1.0f / lb;
    float* opa = O + ((long)b * MROWS + ma) * EMBD + h * DHEAD;
    float* opb = O + ((long)b * MROWS + mb) * EMBD + h * DHEAD;
    #pragma unroll
    for (int p = 0; p < 4; p++) {
        float2 x0 = unpack2(acca[2*p]);
        float2 x1 = unpack2(acca[2*p+1]);
        *(float4*)(opa + p * 4) = make_float4(x0.x*inva, x0.y*inva, x1.x*inva, x1.y*inva);
        float2 y0 = unpack2(accb[2*p]);
        float2 y1 = unpack2(accb[2*p+1]);
        *(float4*)(opb + p * 4) = make_float4(y0.x*invb, y0.y*invb, y1.x*invb, y1.y*invb);
    }
}

// =================== score2: 4 full col tiles, scalar epilogue =============
// out/mask rows have stride 513 (odd) -> epilogue must use scalar accesses.
__global__ void __launch_bounds__(256, 2)
score2_kernel(const float* __restrict__ MH, const float* __restrict__ jobs,
              const float* __restrict__ skip, const float* __restrict__ mask,
              float* __restrict__ out, float* __restrict__ sums)
{
    __shared__ float As[2][BK][ASTRIDE];
    __shared__ float Bs[2][BK][BN + 4];
    __shared__ float red[256];

    const int tid  = threadIdx.x;
    const int b    = blockIdx.z;
    const int col0 = blockIdx.x * BN;   // 0,128,256,384 -> t <= 511 always

    const int a_row = tid >> 1;
    const int a_k   = (tid & 1) * 8;
    const int tx = tid & 15;
    const int ty = tid >> 4;

    const float* arow = MH + ((long)b * MROWS + a_row) * EMBD;

    const int t_l = tid >> 1;
    const float* brow = jobs_row(jobs, skip, b, col0 + t_l);

    float4 av0, av1, bv0, bv1;
    av0 = *(const float4*)(arow + a_k);
    av1 = *(const float4*)(arow + a_k + 4);
    bv0 = *(const float4*)(brow + a_k);
    bv1 = *(const float4*)(brow + a_k + 4);
    As[0][a_k+0][a_row]=av0.x; As[0][a_k+1][a_row]=av0.y;
    As[0][a_k+2][a_row]=av0.z; As[0][a_k+3][a_row]=av0.w;
    As[0][a_k+4][a_row]=av1.x; As[0][a_k+5][a_row]=av1.y;
    As[0][a_k+6][a_row]=av1.z; As[0][a_k+7][a_row]=av1.w;
    Bs[0][a_k+0][t_l]=bv0.x; Bs[0][a_k+1][t_l]=bv0.y;
    Bs[0][a_k+2][t_l]=bv0.z; Bs[0][a_k+3][t_l]=bv0.w;
    Bs[0][a_k+4][t_l]=bv1.x; Bs[0][a_k+5][t_l]=bv1.y;
    Bs[0][a_k+6][t_l]=bv1.z; Bs[0][a_k+7][t_l]=bv1.w;
    __syncthreads();

    ull acc2[8][4] = {};

    #pragma unroll 1
    for (int ks = 0; ks < EMBD / BK; ks++) {
        const int cur = ks & 1;
        const bool has_next = (ks < EMBD / BK - 1);
        if (has_next) {
            const int k0 = (ks + 1) * BK;
            av0 = *(const float4*)(arow + k0 + a_k);
            av1 = *(const float4*)(arow + k0 + a_k + 4);
            bv0 = *(const float4*)(brow + k0 + a_k);
            bv1 = *(const float4*)(brow + k0 + a_k + 4);
        }
        GEMM_MICRO(cur)
        if (has_next) {
            const int nxt = 1 - cur;
            As[nxt][a_k+0][a_row]=av0.x; As[nxt][a_k+1][a_row]=av0.y;
            As[nxt][a_k+2][a_row]=av0.z; As[nxt][a_k+3][a_row]=av0.w;
            As[nxt][a_k+4][a_row]=av1.x; As[nxt][a_k+5][a_row]=av1.y;
            As[nxt][a_k+6][a_row]=av1.z; As[nxt][a_k+7][a_row]=av1.w;
            Bs[nxt][a_k+0][t_l]=bv0.x; Bs[nxt][a_k+1][t_l]=bv0.y;
            Bs[nxt][a_k+2][t_l]=bv0.z; Bs[nxt][a_k+3][t_l]=bv0.w;
            Bs[nxt][a_k+4][t_l]=bv1.x; Bs[nxt][a_k+5][t_l]=bv1.y;
            Bs[nxt][a_k+6][t_l]=bv1.z; Bs[nxt][a_k+7][t_l]=bv1.w;
        }
        __syncthreads();
    }

    float lsum = 0.0f;
    #pragma unroll
    for (int half = 0; half < 2; half++) {
        #pragma unroll
        for (int i = 0; i < 4; i++) {
            const int m = half * 64 + ty * 4 + i;
            const int ai = half * 4 + i;
            const long rowbase = (long)b * OUT_PER_B + (long)m * TTOK;
            #pragma unroll
            for (int jh = 0; jh < 2; jh++) {
                const int t = col0 + jh * 64 + tx * 4;
                float2 v0 = unpack2(acc2[ai][jh * 2 + 0]);
                float2 v1 = unpack2(acc2[ai][jh * 2 + 1]);
                float vv[4] = {v0.x, v0.y, v1.x, v1.y};
                #pragma unroll
                for (int e = 0; e < 4; e++) {
                    const long li = rowbase + t + e;
                    const float y = __expf(10.0f * tanh_fast(vv[e] * 0.0625f) + mask[li]);
                    out[li] = y;
                    lsum += y;
                }
            }
        }
    }

    red[tid] = lsum;
    __syncthreads();
    #pragma unroll
    for (int s = 128; s > 0; s >>= 1) {
        if (tid < s) red[tid] += red[tid + s];
        __syncthreads();
    }
    if (tid == 0) atomicAdd(&sums[b], red[0]);
}

// =================== t=512 column tail: 64 blocks x 128 thr ================
__global__ void __launch_bounds__(128)
tail_kernel(const float* __restrict__ MH, const float* __restrict__ jobs,
            const float* __restrict__ mask, float* __restrict__ out,
            float* __restrict__ sums)
{
    __shared__ float jrow[EMBD];
    __shared__ float red[128];

    const int b = blockIdx.x;
    const int m = threadIdx.x;

    const float* jr = jobs + ((long)b * JJOBS + 511) * EMBD;
    *(float2*)&jrow[m * 2] = *(const float2*)(jr + m * 2);
    __syncthreads();

    const float* mh = MH + ((long)b * MROWS + m) * EMBD;
    ull d2 = bcast2(0.0f);
    #pragma unroll
    for (int k = 0; k < EMBD; k += 8) {
        ulonglong2 a = *(const ulonglong2*)(mh + k);
        ulonglong2 a2 = *(const ulonglong2*)(mh + k + 4);
        ulonglong2 w = *(const ulonglong2*)&jrow[k];
        ulonglong2 w2 = *(const ulonglong2*)&jrow[k + 4];
        d2 = fma2(a.x, w.x, d2);
        d2 = fma2(a.y, w.y, d2);
        d2 = fma2(a2.x, w2.x, d2);
        d2 = fma2(a2.y, w2.y, d2);
    }
    float2 f = unpack2(d2);
    const float sc = (f.x + f.y) * 0.0625f;
    const long li = (long)b * OUT_PER_B + (long)m * TTOK + 512;
    const float y = __expf(10.0f * tanh_fast(sc) + mask[li]);
    out[li] = y;

    red[m] = y;
    __syncthreads();
    #pragma unroll
    for (int s = 64; s > 0; s >>= 1) {
        if (m < s) red[m] += red[m + s];
        __syncthreads();
    }
    if (m == 0) atomicAdd(&sums[b], red[0]);
}

// =================== normalize =======================
__global__ void __launch_bounds__(256)
norm_kernel(float4* __restrict__ out, const float* __restrict__ sums)
{
    const int b = blockIdx.y;
    const long per_b4 = OUT_PER_B / 4;
    const long idx = (long)blockIdx.x * blockDim.x + threadIdx.x;
    if (idx < per_b4) {
        const float inv = 1.0f / sums[b];
        float4 v = out[(long)b * per_b4 + idx];
        v.x *= inv; v.y *= inv; v.z *= inv; v.w *= inv;
        out[(long)b * per_b4 + idx] = v;
    }
}

// =================== launch ===================
extern "C" void kernel_launch(void* const* d_in, const int* in_sizes, int n_in,
                              void* d_out, int out_size)
{
    const float* machine = (const float*)d_in[0];
    const float* jobs    = (const float*)d_in[1];
    const float* mask    = (const float*)d_in[2];
    const float* Wq3     = (const float*)d_in[3];
    const float* Wk      = (const float*)d_in[4];
    const float* Wv      = (const float*)d_in[5];
    const float* Wc      = (const float*)d_in[6];
    const float* bc      = (const float*)d_in[7];
    const float* skip    = (const float*)d_in[8];
    float* out = (float*)d_out;

    float *Qp, *Kp, *Vp, *Op, *MHp, *Sp;
    cudaGetSymbolAddress((void**)&Qp,  g_Q);
    cudaGetSymbolAddress((void**)&Kp,  g_K);
    cudaGetSymbolAddress((void**)&Vp,  g_V);
    cudaGetSymbolAddress((void**)&Op,  g_O);
    cudaGetSymbolAddress((void**)&MHp, g_MH);
    cudaGetSymbolAddress((void**)&Sp,  g_SUM);

    const int kv_tiles = (BATCH * TTOK + BM - 1) / BM;   // 257
    proj_kernel<<<dim3(EMBD / BN, kv_tiles, 3), 256>>>(
        jobs, skip, machine, Wk, Wv, Wq3, Kp, Vp, Qp, Sp);

    attn_kernel<<<dim3(HEADS, BATCH), 64>>>(Qp, Kp, Vp, Op);

    wc_kernel<<<dim3(EMBD / BN, (BATCH * MROWS) / WBM), 256>>>(Op, Wc, bc, MHp);

    score2_kernel<<<dim3(4, 1, BATCH), 256>>>(MHp, jobs, skip, mask, out, Sp);
    tail_kernel<<<BATCH, 128>>>(MHp, jobs, mask, out, Sp);

    const int per_b4 = OUT_PER_B / 4;
    norm_kernel<<<dim3((per_b4 + 255) / 256, BATCH), 256>>>((float4*)out, Sp);
}

// round 13
// speedup vs baseline: 1.3098x; 1.1465x over previous
#include <cuda_runtime.h>
#include <cuda_bf16.h>
#include <math.h>
#include <stdint.h>

#define EMBD   256
#define HEADS  16
#define DHEAD  16
#define BATCH  64
#define MROWS  128
#define JJOBS  512
#define TTOK   513
#define OUT_PER_B (MROWS * TTOK)   // 65664

// X matrix (bf16 hi/lo): rows [0,32832) = jobs-virtual, [32832,32896) zero pad,
// [32896, 41088) = machine
#define XJOBS   32832
#define XMACH0  32896
#define XROWS   41088

typedef unsigned long long ull;

__device__ float g_Q [BATCH * MROWS * EMBD];
__device__ float g_K [BATCH * TTOK  * EMBD];
__device__ float g_V [BATCH * TTOK  * EMBD];
__device__ float g_O [BATCH * MROWS * EMBD];
__device__ float g_MH[BATCH * MROWS * EMBD];
__device__ float g_SUM[BATCH];
__device__ __nv_bfloat16 g_Xh[(long)XROWS * EMBD];
__device__ __nv_bfloat16 g_Xl[(long)XROWS * EMBD];
__device__ __nv_bfloat16 g_Wh[3 * EMBD * EMBD];   // [z][n][k]
__device__ __nv_bfloat16 g_Wl[3 * EMBD * EMBD];

// ---------------- packed f32x2 helpers (sm_103a) ----------------
__device__ __forceinline__ ull fma2(ull a, ull b, ull c) {
    ull d; asm("fma.rn.f32x2 %0, %1, %2, %3;" : "=l"(d) : "l"(a), "l"(b), "l"(c));
    return d;
}
__device__ __forceinline__ ull mul2(ull a, ull b) {
    ull d; asm("mul.rn.f32x2 %0, %1, %2;" : "=l"(d) : "l"(a), "l"(b));
    return d;
}
__device__ __forceinline__ ull bcast2(float x) {
    ull d; asm("mov.b64 %0, {%1, %2};" : "=l"(d) : "f"(x), "f"(x));
    return d;
}
__device__ __forceinline__ float2 unpack2(ull v) {
    float2 f; asm("mov.b64 {%0, %1}, %2;" : "=f"(f.x), "=f"(f.y) : "l"(v));
    return f;
}
__device__ __forceinline__ float tanh_fast(float x) {
    const float e = __expf(2.0f * x);
    return 1.0f - __fdividef(2.0f, e + 1.0f);
}

__device__ __forceinline__ const float* jobs_row(const float* __restrict__ jobs,
                                                 const float* __restrict__ skip,
                                                 int b, int t) {
    return (t == 0) ? skip : jobs + ((long)b * JJOBS + (t - 1)) * EMBD;
}

// mma.sync m16n8k16 row.col bf16 -> f32 (sm_80+, works on sm_103 plain)
__device__ __forceinline__ void mma_bf16(float* c, const uint32_t* a,
                                         uint32_t b0, uint32_t b1) {
    asm volatile(
        "mma.sync.aligned.m16n8k16.row.col.f32.bf16.bf16.f32 "
        "{%0,%1,%2,%3}, {%4,%5,%6,%7}, {%8,%9}, {%0,%1,%2,%3};"
        : "+f"(c[0]), "+f"(c[1]), "+f"(c[2]), "+f"(c[3])
        : "r"(a[0]), "r"(a[1]), "r"(a[2]), "r"(a[3]), "r"(b0), "r"(b1));
}

// =================== convert W -> bf16 hi/lo, transposed to [N][K] =========
__global__ void __launch_bounds__(256)
convert_w_kernel(const float* __restrict__ Wk, const float* __restrict__ Wv,
                 const float* __restrict__ Wq,
                 __nv_bfloat16* __restrict__ Wh, __nv_bfloat16* __restrict__ Wl)
{
    __shared__ float tile[32][33];
    const int z = blockIdx.z;
    const float* W = (z == 0) ? Wk : (z == 1) ? Wv : Wq;
    const int kb = blockIdx.y * 32;
    const int nb = blockIdx.x * 32;
    const int tx = threadIdx.x & 31;
    const int ty = threadIdx.x >> 5;   // 0..7

    #pragma unroll
    for (int i = 0; i < 32; i += 8)
        tile[ty + i][tx] = W[(long)(kb + ty + i) * EMBD + nb + tx];
    __syncthreads();
    #pragma unroll
    for (int i = 0; i < 32; i += 8) {
        const int n = nb + ty + i;
        const int k = kb + tx;
        const float w = tile[tx][ty + i];
        const __nv_bfloat16 hi = __float2bfloat16_rn(w);
        const __nv_bfloat16 lo = __float2bfloat16_rn(w - __bfloat162float(hi));
        const long idx = (long)z * EMBD * EMBD + (long)n * EMBD + k;
        Wh[idx] = hi;
        Wl[idx] = lo;
    }
}

// =================== convert X (jobs-virtual + machine) -> bf16 hi/lo ======
__global__ void __launch_bounds__(256)
convert_x_kernel(const float* __restrict__ jobs, const float* __restrict__ skip,
                 const float* __restrict__ machine,
                 __nv_bfloat16* __restrict__ Xh, __nv_bfloat16* __restrict__ Xl,
                 float* __restrict__ sums)
{
    if (blockIdx.x == 0 && threadIdx.x < BATCH) sums[threadIdx.x] = 0.0f;

    const long gid = (long)blockIdx.x * 256 + threadIdx.x;   // 1 thread : 8 elems
    const long total = (long)XROWS * 32;
    if (gid >= total) return;
    const int row = (int)(gid >> 5);
    const int seg = ((int)gid & 31) * 8;

    float v[8] = {};
    const float* src = nullptr;
    if (row < XJOBS) {
        const int b = row / TTOK;
        const int t = row - b * TTOK;
        src = jobs_row(jobs, skip, b, t);
    } else if (row >= XMACH0) {
        src = machine + (long)(row - XMACH0) * EMBD;
    }
    if (src) {
        float4 a = *(const float4*)(src + seg);
        float4 c = *(const float4*)(src + seg + 4);
        v[0]=a.x; v[1]=a.y; v[2]=a.z; v[3]=a.w;
        v[4]=c.x; v[5]=c.y; v[6]=c.z; v[7]=c.w;
    }
    __nv_bfloat16 h[8], l[8];
    #pragma unroll
    for (int i = 0; i < 8; i++) {
        h[i] = __float2bfloat16_rn(v[i]);
        l[i] = __float2bfloat16_rn(v[i] - __bfloat162float(h[i]));
    }
    const long o = (long)row * EMBD + seg;
    *(uint4*)(Xh + o) = *(const uint4*)h;
    *(uint4*)(Xl + o) = *(const uint4*)l;
}

// =================== HMMA projection GEMM ==================================
// z=0: K = Xjobs @ Wk ; z=1: V = Xjobs @ Wv ; z=2: Q = Xmach @ Wq
// C = Ah*Bh + Ah*Bl + Al*Bh (bf16 split, fp32 accum in registers)
// Block: 128x128 tile, 256 thr (8 warps of 32x64). K chunked by 64.
#define PADK   72          // 64 + 8 bf16: conflict-free fragment LDS
#define TILE_B (128 * PADK * 2)   // bytes per tile = 18432
#define OFF_AH 0
#define OFF_AL (TILE_B)
#define OFF_BH (2 * TILE_B)
#define OFF_BL (3 * TILE_B)
#define PROJ_SMEM (4 * TILE_B)    // 73728

__global__ void __launch_bounds__(256, 2)
proj_wmma_kernel(const __nv_bfloat16* __restrict__ Xh,
                 const __nv_bfloat16* __restrict__ Xl,
                 const __nv_bfloat16* __restrict__ Wh,
                 const __nv_bfloat16* __restrict__ Wl,
                 float* __restrict__ Kout, float* __restrict__ Vout,
                 float* __restrict__ Qout)
{
    extern __shared__ char smem[];
    const int z = blockIdx.z;
    const int row_tiles = (z == 2) ? 64 : 257;
    if ((int)blockIdx.y >= row_tiles) return;

    const int tid  = threadIdx.x;
    const int warp = tid >> 5;
    const int lane = tid & 31;
    const int wm = warp & 3;         // 0..3 (row group of 32)
    const int wn = warp >> 2;        // 0..1 (col group of 64)
    const int g   = lane >> 2;       // 0..7
    const int tig = lane & 3;        // 0..3

    const int xrow0 = blockIdx.y * 128 + ((z == 2) ? XMACH0 : 0);
    const int col0  = blockIdx.x * 128;
    const int crow0 = blockIdx.y * 128;
    const int cvalid = (z == 2) ? (BATCH * MROWS) : XJOBS;
    float* C = (z == 0) ? Kout : (z == 1) ? Vout : Qout;

    const __nv_bfloat16* Wz = Wh + (long)z * EMBD * EMBD;
    const __nv_bfloat16* Wzl = Wl + (long)z * EMBD * EMBD;

    // loader mapping: thread -> (row, half-row segment)
    const int lrow = tid >> 1;             // 0..127
    const int lseg = (tid & 1) * 32;       // bf16 offset 0 or 32

    float acc[2][8][4] = {};

    #pragma unroll 1
    for (int kc = 0; kc < 4; kc++) {
        const int ko0 = kc * 64;
        // stage 4 tiles: 128 rows x 64 bf16 each (row stride PADK)
        {
            const __nv_bfloat16* gAh = Xh + (long)(xrow0 + lrow) * EMBD + ko0 + lseg;
            const __nv_bfloat16* gAl = Xl + (long)(xrow0 + lrow) * EMBD + ko0 + lseg;
            const __nv_bfloat16* gBh = Wz  + (long)(col0 + lrow) * EMBD + ko0 + lseg;
            const __nv_bfloat16* gBl = Wzl + (long)(col0 + lrow) * EMBD + ko0 + lseg;
            char* sAh = smem + OFF_AH + lrow * (PADK * 2) + lseg * 2;
            char* sAl = smem + OFF_AL + lrow * (PADK * 2) + lseg * 2;
            char* sBh = smem + OFF_BH + lrow * (PADK * 2) + lseg * 2;
            char* sBl = smem + OFF_BL + lrow * (PADK * 2) + lseg * 2;
            #pragma unroll
            for (int j = 0; j < 4; j++) {
                *(uint4*)(sAh + j * 16) = *(const uint4*)(gAh + j * 8);
                *(uint4*)(sAl + j * 16) = *(const uint4*)(gAl + j * 8);
                *(uint4*)(sBh + j * 16) = *(const uint4*)(gBh + j * 8);
                *(uint4*)(sBl + j * 16) = *(const uint4*)(gBl + j * 8);
            }
        }
        __syncthreads();

        #pragma unroll
        for (int ks = 0; ks < 4; ks++) {
            const int ko = ks * 16;
            // A fragments (hi & lo) for 2 m16 tiles
            uint32_t ahf[2][4], alf[2][4];
            #pragma unroll
            for (int mt = 0; mt < 2; mt++) {
                const int r0 = wm * 32 + mt * 16 + g;
                const char* bAh = smem + OFF_AH;
                const char* bAl = smem + OFF_AL;
                const int c0 = (ko + 2 * tig) * 2;
                const int c8 = (ko + 8 + 2 * tig) * 2;
                ahf[mt][0] = *(const uint32_t*)(bAh + r0 * (PADK*2) + c0);
                ahf[mt][1] = *(const uint32_t*)(bAh + (r0+8) * (PADK*2) + c0);
                ahf[mt][2] = *(const uint32_t*)(bAh + r0 * (PADK*2) + c8);
                ahf[mt][3] = *(const uint32_t*)(bAh + (r0+8) * (PADK*2) + c8);
                alf[mt][0] = *(const uint32_t*)(bAl + r0 * (PADK*2) + c0);
                alf[mt][1] = *(const uint32_t*)(bAl + (r0+8) * (PADK*2) + c0);
                alf[mt][2] = *(const uint32_t*)(bAl + r0 * (PADK*2) + c8);
                alf[mt][3] = *(const uint32_t*)(bAl + (r0+8) * (PADK*2) + c8);
            }
            #pragma unroll
            for (int nt = 0; nt < 8; nt++) {
                const int nr = wn * 64 + nt * 8 + g;
                const char* bBh = smem + OFF_BH;
                const char* bBl = smem + OFF_BL;
                const int c0 = (ko + 2 * tig) * 2;
                const int c8 = (ko + 8 + 2 * tig) * 2;
                const uint32_t bh0 = *(const uint32_t*)(bBh + nr * (PADK*2) + c0);
                const uint32_t bh1 = *(const uint32_t*)(bBh + nr * (PADK*2) + c8);
                const uint32_t bl0 = *(const uint32_t*)(bBl + nr * (PADK*2) + c0);
                const uint32_t bl1 = *(const uint32_t*)(bBl + nr * (PADK*2) + c8);
                #pragma unroll
                for (int mt = 0; mt < 2; mt++) {
                    mma_bf16(acc[mt][nt], ahf[mt], bh0, bh1);
                    mma_bf16(acc[mt][nt], ahf[mt], bl0, bl1);
                    mma_bf16(acc[mt][nt], alf[mt], bh0, bh1);
                }
            }
        }
        __syncthreads();
    }

    // epilogue: c0,c1 -> row g, cols 2*tig..+1 ; c2,c3 -> row g+8
    #pragma unroll
    for (int mt = 0; mt < 2; mt++) {
        const int r_lo = crow0 + wm * 32 + mt * 16 + g;
        const int r_hi = r_lo + 8;
        #pragma unroll
        for (int nt = 0; nt < 8; nt++) {
            const int col = col0 + wn * 64 + nt * 8 + 2 * tig;
            if (r_lo < cvalid)
                *(float2*)(C + (long)r_lo * EMBD + col) =
                    make_float2(acc[mt][nt][0], acc[mt][nt][1]);
            if (r_hi < cvalid)
                *(float2*)(C + (long)r_hi * EMBD + col) =
                    make_float2(acc[mt][nt][2], acc[mt][nt][3]);
        }
    }
}

// =================== attention: 2 queries/thread, 64-thread blocks =========
__global__ void __launch_bounds__(64)
attn_kernel(const float* __restrict__ Q, const float* __restrict__ K,
            const float* __restrict__ V, float* __restrict__ O)
{
    __shared__ float Ks[128][DHEAD];
    __shared__ float Vs[128][DHEAD];

    const int h = blockIdx.x;
    const int b = blockIdx.y;
    const int tid = threadIdx.x;
    const int ma = tid;
    const int mb = tid + 64;

    ull qa[8], qb[8];
    {
        const float* qpa = Q + ((long)b * MROWS + ma) * EMBD + h * DHEAD;
        const float* qpb = Q + ((long)b * MROWS + mb) * EMBD + h * DHEAD;
        #pragma unroll
        for (int p = 0; p < 4; p++) {
            ulonglong2 va = *(const ulonglong2*)(qpa + p * 4);
            ulonglong2 vb = *(const ulonglong2*)(qpb + p * 4);
            qa[2*p] = va.x; qa[2*p+1] = va.y;
            qb[2*p] = vb.x; qb[2*p+1] = vb.y;
        }
    }

    float la = 0.0f, lb = 0.0f;
    ull acca[8] = {}, accb[8] = {};

    #pragma unroll 1
    for (int c = 0; c < 4; c++) {
        const int t0 = c * 128;
        __syncthreads();
        #pragma unroll
        for (int j = 0; j < 8; j++) {
            const int idx = tid + j * 64;
            const int rr = idx >> 2, cc = (idx & 3) * 4;
            const long base = ((long)b * TTOK + t0 + rr) * EMBD + h * DHEAD + cc;
            *(float4*)&Ks[rr][cc] = *(const float4*)(K + base);
            *(float4*)&Vs[rr][cc] = *(const float4*)(V + base);
        }
        __syncthreads();

        #pragma unroll 1
        for (int tt = 0; tt < 128; tt += 4) {
            float sa[4], sb[4];
            #pragma unroll
            for (int j = 0; j < 4; j++) {
                const ulonglong2* kp = (const ulonglong2*)Ks[tt + j];
                ulonglong2 k0 = kp[0], k1 = kp[1], k2v = kp[2], k3 = kp[3];
                ull da = mul2(qa[0], k0.x);
                ull db = mul2(qb[0], k0.x);
                da = fma2(qa[1], k0.y, da);  db = fma2(qb[1], k0.y, db);
                da = fma2(qa[2], k1.x, da);  db = fma2(qb[2], k1.x, db);
                da = fma2(qa[3], k1.y, da);  db = fma2(qb[3], k1.y, db);
                da = fma2(qa[4], k2v.x, da); db = fma2(qb[4], k2v.x, db);
                da = fma2(qa[5], k2v.y, da); db = fma2(qb[5], k2v.y, db);
                da = fma2(qa[6], k3.x, da);  db = fma2(qb[6], k3.x, db);
                da = fma2(qa[7], k3.y, da);  db = fma2(qb[7], k3.y, db);
                float2 fa = unpack2(da), fb = unpack2(db);
                sa[j] = (fa.x + fa.y) * 0.25f;
                sb[j] = (fb.x + fb.y) * 0.25f;
            }
            float pa[4], pb[4];
            #pragma unroll
            for (int j = 0; j < 4; j++) {
                pa[j] = __expf(sa[j]); la += pa[j];
                pb[j] = __expf(sb[j]); lb += pb[j];
            }
            #pragma unroll
            for (int j = 0; j < 4; j++) {
                const ull pba = bcast2(pa[j]);
                const ull pbb = bcast2(pb[j]);
                const ulonglong2* vp = (const ulonglong2*)Vs[tt + j];
                ulonglong2 v0 = vp[0], v1 = vp[1];
                acca[0] = fma2(pba, v0.x, acca[0]); accb[0] = fma2(pbb, v0.x, accb[0]);
                acca[1] = fma2(pba, v0.y, acca[1]); accb[1] = fma2(pbb, v0.y, accb[1]);
                acca[2] = fma2(pba, v1.x, acca[2]); accb[2] = fma2(pbb, v1.x, accb[2]);
                acca[3] = fma2(pba, v1.y, acca[3]); accb[3] = fma2(pbb, v1.y, accb[3]);
                ulonglong2 v2v = vp[2], v3 = vp[3];
                acca[4] = fma2(pba, v2v.x, acca[4]); accb[4] = fma2(pbb, v2v.x, accb[4]);
                acca[5] = fma2(pba, v2v.y, acca[5]); accb[5] = fma2(pbb, v2v.y, accb[5]);
                acca[6] = fma2(pba, v3.x, acca[6]);  accb[6] = fma2(pbb, v3.x, accb[6]);
                acca[7] = fma2(pba, v3.y, acca[7]);  accb[7] = fma2(pbb, v3.y, accb[7]);
            }
        }
    }

    // tail token t = 512
    {
        const long base = ((long)b * TTOK + 512) * EMBD + h * DHEAD;
        const ulonglong2* kp = (const ulonglong2*)(K + base);
        ulonglong2 k0 = kp[0], k1 = kp[1], k2v = kp[2], k3 = kp[3];
        ull da = mul2(qa[0], k0.x);
        ull db = mul2(qb[0], k0.x);
        da = fma2(qa[1], k0.y, da);  db = fma2(qb[1], k0.y, db);
        da = fma2(qa[2], k1.x, da);  db = fma2(qb[2], k1.x, db);
        da = fma2(qa[3], k1.y, da);  db = fma2(qb[3], k1.y, db);
        da = fma2(qa[4], k2v.x, da); db = fma2(qb[4], k2v.x, db);
        da = fma2(qa[5], k2v.y, da); db = fma2(qb[5], k2v.y, db);
        da = fma2(qa[6], k3.x, da);  db = fma2(qb[6], k3.x, db);
        da = fma2(qa[7], k3.y, da);  db = fma2(qb[7], k3.y, db);
        float2 fa = unpack2(da), fb = unpack2(db);
        const float pa = __expf((fa.x + fa.y) * 0.25f);
        const float pb = __expf((fb.x + fb.y) * 0.25f);
        la += pa; lb += pb;
        const ull pba = bcast2(pa);
        const ull pbb = bcast2(pb);
        const ulonglong2* vp = (const ulonglong2*)(V + base);
        ulonglong2 v0 = vp[0], v1 = vp[1], v2v = vp[2], v3 = vp[3];
        acca[0] = fma2(pba, v0.x,  acca[0]); accb[0] = fma2(pbb, v0.x,  accb[0]);
        acca[1] = fma2(pba, v0.y,  acca[1]); accb[1] = fma2(pbb, v0.y,  accb[1]);
        acca[2] = fma2(pba, v1.x,  acca[2]); accb[2] = fma2(pbb, v1.x,  accb[2]);
        acca[3] = fma2(pba, v1.y,  acca[3]); accb[3] = fma2(pbb, v1.y,  accb[3]);
        acca[4] = fma2(pba, v2v.x, acca[4]); accb[4] = fma2(pbb, v2v.x, accb[4]);
        acca[5] = fma2(pba, v2v.y, acca[5]); accb[5] = fma2(pbb, v2v.y, accb[5]);
        acca[6] = fma2(pba, v3.x,  acca[6]); accb[6] = fma2(pbb, v3.x,  accb[6]);
        acca[7] = fma2(pba, v3.y,  acca[7]); accb[7] = fma2(pbb, v3.y,  accb[7]);
    }

    const float inva = 1.0f / la;
    const float invb = 1.0f / lb;
    float* opa = O + ((long)b * MROWS + ma) * EMBD + h * DHEAD;
    float* opb = O + ((long)b * MROWS + mb) * EMBD + h * DHEAD;
    #pragma unroll
    for (int p = 0; p < 4; p++) {
        float2 x0 = unpack2(acca[2*p]);
        float2 x1 = unpack2(acca[2*p+1]);
        *(float4*)(opa + p * 4) = make_float4(x0.x*inva, x0.y*inva, x1.x*inva, x1.y*inva);
        float2 y0 = unpack2(accb[2*p]);
        float2 y1 = unpack2(accb[2*p+1]);
        *(float4*)(opb + p * 4) = make_float4(y0.x*invb, y0.y*invb, y1.x*invb, y1.y*invb);
    }
}

// =================== Wc projection (+bias), 64x128 tiles ====================
#define BK 16
#define BN 128
#define WBM 64
__global__ void __launch_bounds__(256)
wc_kernel(const float* __restrict__ X, const float* __restrict__ W,
          const float* __restrict__ bias, float* __restrict__ C)
{
    __shared__ float As[2][BK][WBM + 4];
    __shared__ float Bs[2][BK][BN];

    const int tid  = threadIdx.x;
    const int row0 = blockIdx.y * WBM;
    const int col0 = blockIdx.x * BN;

    const int a_row = tid >> 2;
    const int a_k   = (tid & 3) * 4;
    const int b_k   = tid >> 4;
    const int b_n   = (tid & 15) * 8;
    const int tx = tid & 15;
    const int ty = tid >> 4;

    const float* xrow = X + (long)(row0 + a_row) * EMBD;
    const float* wptr = W + (long)b_k * EMBD + col0 + b_n;

    float4 av, bv0, bv1;
    av  = *(const float4*)(xrow + a_k);
    bv0 = *(const float4*)(wptr);
    bv1 = *(const float4*)(wptr + 4);
    As[0][a_k+0][a_row]=av.x; As[0][a_k+1][a_row]=av.y;
    As[0][a_k+2][a_row]=av.z; As[0][a_k+3][a_row]=av.w;
    *(float4*)&Bs[0][b_k][b_n]     = bv0;
    *(float4*)&Bs[0][b_k][b_n + 4] = bv1;
    __syncthreads();

    ull acc2[4][4] = {};

    #pragma unroll 1
    for (int ks = 0; ks < EMBD / BK; ks++) {
        const int cur = ks & 1;
        const bool has_next = (ks < EMBD / BK - 1);
        if (has_next) {
            const int k0 = (ks + 1) * BK;
            av  = *(const float4*)(xrow + k0 + a_k);
            bv0 = *(const float4*)(wptr + (long)k0 * EMBD);
            bv1 = *(const float4*)(wptr + (long)k0 * EMBD + 4);
        }
        #pragma unroll
        for (int kk = 0; kk < BK; kk++) {
            float4 a0 = *(const float4*)&As[cur][kk][ty * 4];
            ulonglong2 p0 = *(const ulonglong2*)&Bs[cur][kk][tx * 4];
            ulonglong2 p1 = *(const ulonglong2*)&Bs[cur][kk][64 + tx * 4];
            ull B2[4] = {p0.x, p0.y, p1.x, p1.y};
            float a[4] = {a0.x, a0.y, a0.z, a0.w};
            #pragma unroll
            for (int i = 0; i < 4; i++) {
                const ull ai = bcast2(a[i]);
                #pragma unroll
                for (int j = 0; j < 4; j++)
                    acc2[i][j] = fma2(ai, B2[j], acc2[i][j]);
            }
        }
        if (has_next) {
            const int nxt = 1 - cur;
            As[nxt][a_k+0][a_row]=av.x; As[nxt][a_k+1][a_row]=av.y;
            As[nxt][a_k+2][a_row]=av.z; As[nxt][a_k+3][a_row]=av.w;
            *(float4*)&Bs[nxt][b_k][b_n]     = bv0;
            *(float4*)&Bs[nxt][b_k][b_n + 4] = bv1;
        }
        __syncthreads();
    }

    float4 bb0 = *(const float4*)(bias + col0 + tx * 4);
    float4 bb1 = *(const float4*)(bias + col0 + 64 + tx * 4);

    #pragma unroll
    for (int i = 0; i < 4; i++) {
        const int r = row0 + ty * 4 + i;
        float2 c0 = unpack2(acc2[i][0]);
        float2 c1 = unpack2(acc2[i][1]);
        float2 c2 = unpack2(acc2[i][2]);
        float2 c3 = unpack2(acc2[i][3]);
        float4 o0 = make_float4(c0.x+bb0.x, c0.y+bb0.y, c1.x+bb0.z, c1.y+bb0.w);
        float4 o1 = make_float4(c2.x+bb1.x, c2.y+bb1.y, c3.x+bb1.z, c3.y+bb1.w);
        *(float4*)(C + (long)r * EMBD + col0 + tx * 4)      = o0;
        *(float4*)(C + (long)r * EMBD + col0 + 64 + tx * 4) = o1;
    }
}

// =================== score2: 4 full col tiles, scalar epilogue =============
#define BM 128
#define ASTRIDE (BM + 4)
#define GEMM_MICRO(cur)                                                        \
    _Pragma("unroll")                                                          \
    for (int kk = 0; kk < BK; kk++) {                                          \
        float4 a0 = *(const float4*)&As[cur][kk][ty * 4];                      \
        float4 a1 = *(const float4*)&As[cur][kk][64 + ty * 4];                 \
        ulonglong2 p0 = *(const ulonglong2*)&Bs[cur][kk][tx * 4];              \
        ulonglong2 p1 = *(const ulonglong2*)&Bs[cur][kk][64 + tx * 4];         \
        ull B2[4] = {p0.x, p0.y, p1.x, p1.y};                                  \
        float a[8] = {a0.x,a0.y,a0.z,a0.w,a1.x,a1.y,a1.z,a1.w};                \
        _Pragma("unroll")                                                      \
        for (int i = 0; i < 8; i++) {                                          \
            const ull ai = bcast2(a[i]);                                       \
            _Pragma("unroll")                                                  \
            for (int j = 0; j < 4; j++)                                        \
                acc2[i][j] = fma2(ai, B2[j], acc2[i][j]);                      \
        }                                                                      \
    }

__global__ void __launch_bounds__(256, 2)
score2_kernel(const float* __restrict__ MH, const float* __restrict__ jobs,
              const float* __restrict__ skip, const float* __restrict__ mask,
              float* __restrict__ out, float* __restrict__ sums)
{
    __shared__ float As[2][BK][ASTRIDE];
    __shared__ float Bs[2][BK][BN + 4];
    __shared__ float red[256];

    const int tid  = threadIdx.x;
    const int b    = blockIdx.z;
    const int col0 = blockIdx.x * BN;

    const int a_row = tid >> 1;
    const int a_k   = (tid & 1) * 8;
    const int tx = tid & 15;
    const int ty = tid >> 4;

    const float* arow = MH + ((long)b * MROWS + a_row) * EMBD;
    const int t_l = tid >> 1;
    const float* brow = jobs_row(jobs, skip, b, col0 + t_l);

    float4 av0, av1, bv0, bv1;
    av0 = *(const float4*)(arow + a_k);
    av1 = *(const float4*)(arow + a_k + 4);
    bv0 = *(const float4*)(brow + a_k);
    bv1 = *(const float4*)(brow + a_k + 4);
    As[0][a_k+0][a_row]=av0.x; As[0][a_k+1][a_row]=av0.y;
    As[0][a_k+2][a_row]=av0.z; As[0][a_k+3][a_row]=av0.w;
    As[0][a_k+4][a_row]=av1.x; As[0][a_k+5][a_row]=av1.y;
    As[0][a_k+6][a_row]=av1.z; As[0][a_k+7][a_row]=av1.w;
    Bs[0][a_k+0][t_l]=bv0.x; Bs[0][a_k+1][t_l]=bv0.y;
    Bs[0][a_k+2][t_l]=bv0.z; Bs[0][a_k+3][t_l]=bv0.w;
    Bs[0][a_k+4][t_l]=bv1.x; Bs[0][a_k+5][t_l]=bv1.y;
    Bs[0][a_k+6][t_l]=bv1.z; Bs[0][a_k+7][t_l]=bv1.w;
    __syncthreads();

    ull acc2[8][4] = {};

    #pragma unroll 1
    for (int ks = 0; ks < EMBD / BK; ks++) {
        const int cur = ks & 1;
        const bool has_next = (ks < EMBD / BK - 1);
        if (has_next) {
            const int k0 = (ks + 1) * BK;
            av0 = *(const float4*)(arow + k0 + a_k);
            av1 = *(const float4*)(arow + k0 + a_k + 4);
            bv0 = *(const float4*)(brow + k0 + a_k);
            bv1 = *(const float4*)(brow + k0 + a_k + 4);
        }
        GEMM_MICRO(cur)
        if (has_next) {
            const int nxt = 1 - cur;
            As[nxt][a_k+0][a_row]=av0.x; As[nxt][a_k+1][a_row]=av0.y;
            As[nxt][a_k+2][a_row]=av0.z; As[nxt][a_k+3][a_row]=av0.w;
            As[nxt][a_k+4][a_row]=av1.x; As[nxt][a_k+5][a_row]=av1.y;
            As[nxt][a_k+6][a_row]=av1.z; As[nxt][a_k+7][a_row]=av1.w;
            Bs[nxt][a_k+0][t_l]=bv0.x; Bs[nxt][a_k+1][t_l]=bv0.y;
            Bs[nxt][a_k+2][t_l]=bv0.z; Bs[nxt][a_k+3][t_l]=bv0.w;
            Bs[nxt][a_k+4][t_l]=bv1.x; Bs[nxt][a_k+5][t_l]=bv1.y;
            Bs[nxt][a_k+6][t_l]=bv1.z; Bs[nxt][a_k+7][t_l]=bv1.w;
        }
        __syncthreads();
    }

    float lsum = 0.0f;
    #pragma unroll
    for (int half = 0; half < 2; half++) {
        #pragma unroll
        for (int i = 0; i < 4; i++) {
            const int m = half * 64 + ty * 4 + i;
            const int ai = half * 4 + i;
            const long rowbase = (long)b * OUT_PER_B + (long)m * TTOK;
            #pragma unroll
            for (int jh = 0; jh < 2; jh++) {
                const int t = col0 + jh * 64 + tx * 4;
                float2 v0 = unpack2(acc2[ai][jh * 2 + 0]);
                float2 v1 = unpack2(acc2[ai][jh * 2 + 1]);
                float vv[4] = {v0.x, v0.y, v1.x, v1.y};
                #pragma unroll
                for (int e = 0; e < 4; e++) {
                    const long li = rowbase + t + e;
                    const float y = __expf(10.0f * tanh_fast(vv[e] * 0.0625f) + mask[li]);
                    out[li] = y;
                    lsum += y;
                }
            }
        }
    }

    red[tid] = lsum;
    __syncthreads();
    #pragma unroll
    for (int s = 128; s > 0; s >>= 1) {
        if (tid < s) red[tid] += red[tid + s];
        __syncthreads();
    }
    if (tid == 0) atomicAdd(&sums[b], red[0]);
}

// =================== t=512 column tail ================
__global__ void __launch_bounds__(128)
tail_kernel(const float* __restrict__ MH, const float* __restrict__ jobs,
            const float* __restrict__ mask, float* __restrict__ out,
            float* __restrict__ sums)
{
    __shared__ float jrow[EMBD];
    __shared__ float red[128];

    const int b = blockIdx.x;
    const int m = threadIdx.x;

    const float* jr = jobs + ((long)b * JJOBS + 511) * EMBD;
    *(float2*)&jrow[m * 2] = *(const float2*)(jr + m * 2);
    __syncthreads();

    const float* mh = MH + ((long)b * MROWS + m) * EMBD;
    ull d2 = bcast2(0.0f);
    #pragma unroll
    for (int k = 0; k < EMBD; k += 8) {
        ulonglong2 a = *(const ulonglong2*)(mh + k);
        ulonglong2 a2 = *(const ulonglong2*)(mh + k + 4);
        ulonglong2 w = *(const ulonglong2*)&jrow[k];
        ulonglong2 w2 = *(const ulonglong2*)&jrow[k + 4];
        d2 = fma2(a.x, w.x, d2);
        d2 = fma2(a.y, w.y, d2);
        d2 = fma2(a2.x, w2.x, d2);
        d2 = fma2(a2.y, w2.y, d2);
    }
    float2 f = unpack2(d2);
    const float sc = (f.x + f.y) * 0.0625f;
    const long li = (long)b * OUT_PER_B + (long)m * TTOK + 512;
    const float y = __expf(10.0f * tanh_fast(sc) + mask[li]);
    out[li] = y;

    red[m] = y;
    __syncthreads();
    #pragma unroll
    for (int s = 64; s > 0; s >>= 1) {
        if (m < s) red[m] += red[m + s];
        __syncthreads();
    }
    if (m == 0) atomicAdd(&sums[b], red[0]);
}

// =================== normalize =======================
__global__ void __launch_bounds__(256)
norm_kernel(float4* __restrict__ out, const float* __restrict__ sums)
{
    const int b = blockIdx.y;
    const long per_b4 = OUT_PER_B / 4;
    const long idx = (long)blockIdx.x * blockDim.x + threadIdx.x;
    if (idx < per_b4) {
        const float inv = 1.0f / sums[b];
        float4 v = out[(long)b * per_b4 + idx];
        v.x *= inv; v.y *= inv; v.z *= inv; v.w *= inv;
        out[(long)b * per_b4 + idx] = v;
    }
}

// =================== launch ===================
extern "C" void kernel_launch(void* const* d_in, const int* in_sizes, int n_in,
                              void* d_out, int out_size)
{
    const float* machine = (const float*)d_in[0];
    const float* jobs    = (const float*)d_in[1];
    const float* mask    = (const float*)d_in[2];
    const float* Wq3     = (const float*)d_in[3];
    const float* Wk      = (const float*)d_in[4];
    const float* Wv      = (const float*)d_in[5];
    const float* Wc      = (const float*)d_in[6];
    const float* bc      = (const float*)d_in[7];
    const float* skip    = (const float*)d_in[8];
    float* out = (float*)d_out;

    float *Qp, *Kp, *Vp, *Op, *MHp, *Sp;
    __nv_bfloat16 *Xh, *Xl, *Wh, *Wl;
    cudaGetSymbolAddress((void**)&Qp,  g_Q);
    cudaGetSymbolAddress((void**)&Kp,  g_K);
    cudaGetSymbolAddress((void**)&Vp,  g_V);
    cudaGetSymbolAddress((void**)&Op,  g_O);
    cudaGetSymbolAddress((void**)&MHp, g_MH);
    cudaGetSymbolAddress((void**)&Sp,  g_SUM);
    cudaGetSymbolAddress((void**)&Xh,  g_Xh);
    cudaGetSymbolAddress((void**)&Xl,  g_Xl);
    cudaGetSymbolAddress((void**)&Wh,  g_Wh);
    cudaGetSymbolAddress((void**)&Wl,  g_Wl);

    cudaFuncSetAttribute(proj_wmma_kernel,
                         cudaFuncAttributeMaxDynamicSharedMemorySize, PROJ_SMEM);

    // converts (also zeroes sums)
    convert_w_kernel<<<dim3(8, 8, 3), 256>>>(Wk, Wv, Wq3, Wh, Wl);
    {
        const long total = (long)XROWS * 32;
        convert_x_kernel<<<(int)((total + 255) / 256), 256>>>(
            jobs, skip, machine, Xh, Xl, Sp);
    }

    // HMMA projections
    proj_wmma_kernel<<<dim3(2, 257, 3), 256, PROJ_SMEM>>>(
        Xh, Xl, Wh, Wl, Kp, Vp, Qp);

    attn_kernel<<<dim3(HEADS, BATCH), 64>>>(Qp, Kp, Vp, Op);

    wc_kernel<<<dim3(EMBD / BN, (BATCH * MROWS) / WBM), 256>>>(Op, Wc, bc, MHp);

    score2_kernel<<<dim3(4, 1, BATCH), 256>>>(MHp, jobs, skip, mask, out, Sp);
    tail_kernel<<<BATCH, 128>>>(MHp, jobs, mask, out, Sp);

    const int per_b4 = OUT_PER_B / 4;
    norm_kernel<<<dim3((per_b4 + 255) / 256, BATCH), 256>>>((float4*)out, Sp);
}

// round 14
// speedup vs baseline: 1.4397x; 1.0991x over previous
#include <cuda_runtime.h>
#include <cuda_bf16.h>
#include <math.h>
#include <stdint.h>

#define EMBD   256
#define HEADS  16
#define DHEAD  16
#define BATCH  64
#define MROWS  128
#define JJOBS  512
#define TTOK   513
#define OUT_PER_B (MROWS * TTOK)   // 65664

#define XJOBS   32832
#define XMACH0  32896
#define XROWS   41088

typedef unsigned long long ull;

__device__ float g_Q [BATCH * MROWS * EMBD];
__device__ float g_K [BATCH * TTOK  * EMBD];
__device__ float g_V [BATCH * TTOK  * EMBD];
__device__ float g_O [BATCH * MROWS * EMBD];
__device__ float g_MH[BATCH * MROWS * EMBD];
__device__ float g_SUM[BATCH];
__device__ __nv_bfloat16 g_Xh[(long)XROWS * EMBD];
__device__ __nv_bfloat16 g_Xl[(long)XROWS * EMBD];
__device__ __nv_bfloat16 g_Wh[3 * EMBD * EMBD];   // [z][n][k]
__device__ __nv_bfloat16 g_Wl[3 * EMBD * EMBD];

// ---------------- packed f32x2 helpers ----------------
__device__ __forceinline__ ull fma2(ull a, ull b, ull c) {
    ull d; asm("fma.rn.f32x2 %0, %1, %2, %3;" : "=l"(d) : "l"(a), "l"(b), "l"(c));
    return d;
}
__device__ __forceinline__ ull bcast2(float x) {
    ull d; asm("mov.b64 %0, {%1, %2};" : "=l"(d) : "f"(x), "f"(x));
    return d;
}
__device__ __forceinline__ float2 unpack2(ull v) {
    float2 f; asm("mov.b64 {%0, %1}, %2;" : "=f"(f.x), "=f"(f.y) : "l"(v));
    return f;
}
__device__ __forceinline__ float tanh_fast(float x) {
    const float e = __expf(2.0f * x);
    return 1.0f - __fdividef(2.0f, e + 1.0f);
}

__device__ __forceinline__ const float* jobs_row(const float* __restrict__ jobs,
                                                 const float* __restrict__ skip,
                                                 int b, int t) {
    return (t == 0) ? skip : jobs + ((long)b * JJOBS + (t - 1)) * EMBD;
}

// mma.sync m16n8k16 row.col bf16 -> f32
__device__ __forceinline__ void mma_bf16(float* c, const uint32_t* a,
                                         uint32_t b0, uint32_t b1) {
    asm volatile(
        "mma.sync.aligned.m16n8k16.row.col.f32.bf16.bf16.f32 "
        "{%0,%1,%2,%3}, {%4,%5,%6,%7}, {%8,%9}, {%0,%1,%2,%3};"
        : "+f"(c[0]), "+f"(c[1]), "+f"(c[2]), "+f"(c[3])
        : "r"(a[0]), "r"(a[1]), "r"(a[2]), "r"(a[3]), "r"(b0), "r"(b1));
}

__device__ __forceinline__ uint32_t packbf(__nv_bfloat16 a, __nv_bfloat16 b) {
    __nv_bfloat162 t; t.x = a; t.y = b;
    return *(uint32_t*)&t;
}
// split (x,y) into packed bf16 hi and lo residual
__device__ __forceinline__ void split2(float x, float y,
                                       uint32_t& hi, uint32_t& lo) {
    const __nv_bfloat16 hx = __float2bfloat16_rn(x);
    const __nv_bfloat16 hy = __float2bfloat16_rn(y);
    const __nv_bfloat16 lx = __float2bfloat16_rn(x - __bfloat162float(hx));
    const __nv_bfloat16 ly = __float2bfloat16_rn(y - __bfloat162float(hy));
    hi = packbf(hx, hy);
    lo = packbf(lx, ly);
}

// =================== convert W -> bf16 hi/lo, transposed to [N][K] =========
__global__ void __launch_bounds__(256)
convert_w_kernel(const float* __restrict__ Wk, const float* __restrict__ Wv,
                 const float* __restrict__ Wq,
                 __nv_bfloat16* __restrict__ Wh, __nv_bfloat16* __restrict__ Wl)
{
    __shared__ float tile[32][33];
    const int z = blockIdx.z;
    const float* W = (z == 0) ? Wk : (z == 1) ? Wv : Wq;
    const int kb = blockIdx.y * 32;
    const int nb = blockIdx.x * 32;
    const int tx = threadIdx.x & 31;
    const int ty = threadIdx.x >> 5;

    #pragma unroll
    for (int i = 0; i < 32; i += 8)
        tile[ty + i][tx] = W[(long)(kb + ty + i) * EMBD + nb + tx];
    __syncthreads();
    #pragma unroll
    for (int i = 0; i < 32; i += 8) {
        const int n = nb + ty + i;
        const int k = kb + tx;
        const float w = tile[tx][ty + i];
        const __nv_bfloat16 hi = __float2bfloat16_rn(w);
        const __nv_bfloat16 lo = __float2bfloat16_rn(w - __bfloat162float(hi));
        const long idx = (long)z * EMBD * EMBD + (long)n * EMBD + k;
        Wh[idx] = hi;
        Wl[idx] = lo;
    }
}

// =================== convert X -> bf16 hi/lo ======
__global__ void __launch_bounds__(256)
convert_x_kernel(const float* __restrict__ jobs, const float* __restrict__ skip,
                 const float* __restrict__ machine,
                 __nv_bfloat16* __restrict__ Xh, __nv_bfloat16* __restrict__ Xl,
                 float* __restrict__ sums)
{
    if (blockIdx.x == 0 && threadIdx.x < BATCH) sums[threadIdx.x] = 0.0f;

    const long gid = (long)blockIdx.x * 256 + threadIdx.x;
    const long total = (long)XROWS * 32;
    if (gid >= total) return;
    const int row = (int)(gid >> 5);
    const int seg = ((int)gid & 31) * 8;

    float v[8] = {};
    const float* src = nullptr;
    if (row < XJOBS) {
        const int b = row / TTOK;
        const int t = row - b * TTOK;
        src = jobs_row(jobs, skip, b, t);
    } else if (row >= XMACH0) {
        src = machine + (long)(row - XMACH0) * EMBD;
    }
    if (src) {
        float4 a = *(const float4*)(src + seg);
        float4 c = *(const float4*)(src + seg + 4);
        v[0]=a.x; v[1]=a.y; v[2]=a.z; v[3]=a.w;
        v[4]=c.x; v[5]=c.y; v[6]=c.z; v[7]=c.w;
    }
    __nv_bfloat16 h[8], l[8];
    #pragma unroll
    for (int i = 0; i < 8; i++) {
        h[i] = __float2bfloat16_rn(v[i]);
        l[i] = __float2bfloat16_rn(v[i] - __bfloat162float(h[i]));
    }
    const long o = (long)row * EMBD + seg;
    *(uint4*)(Xh + o) = *(const uint4*)h;
    *(uint4*)(Xl + o) = *(const uint4*)l;
}

// =================== HMMA projection GEMM ==================================
#define PADK   72
#define TILE_B (128 * PADK * 2)
#define OFF_AH 0
#define OFF_AL (TILE_B)
#define OFF_BH (2 * TILE_B)
#define OFF_BL (3 * TILE_B)
#define PROJ_SMEM (4 * TILE_B)

__global__ void __launch_bounds__(256, 2)
proj_wmma_kernel(const __nv_bfloat16* __restrict__ Xh,
                 const __nv_bfloat16* __restrict__ Xl,
                 const __nv_bfloat16* __restrict__ Wh,
                 const __nv_bfloat16* __restrict__ Wl,
                 float* __restrict__ Kout, float* __restrict__ Vout,
                 float* __restrict__ Qout)
{
    extern __shared__ char smem[];
    const int z = blockIdx.z;
    const int row_tiles = (z == 2) ? 64 : 257;
    if ((int)blockIdx.y >= row_tiles) return;

    const int tid  = threadIdx.x;
    const int warp = tid >> 5;
    const int lane = tid & 31;
    const int wm = warp & 3;
    const int wn = warp >> 2;
    const int g   = lane >> 2;
    const int tig = lane & 3;

    const int xrow0 = blockIdx.y * 128 + ((z == 2) ? XMACH0 : 0);
    const int col0  = blockIdx.x * 128;
    const int crow0 = blockIdx.y * 128;
    const int cvalid = (z == 2) ? (BATCH * MROWS) : XJOBS;
    float* C = (z == 0) ? Kout : (z == 1) ? Vout : Qout;

    const __nv_bfloat16* Wz = Wh + (long)z * EMBD * EMBD;
    const __nv_bfloat16* Wzl = Wl + (long)z * EMBD * EMBD;

    const int lrow = tid >> 1;
    const int lseg = (tid & 1) * 32;

    float acc[2][8][4] = {};

    #pragma unroll 1
    for (int kc = 0; kc < 4; kc++) {
        const int ko0 = kc * 64;
        {
            const __nv_bfloat16* gAh = Xh + (long)(xrow0 + lrow) * EMBD + ko0 + lseg;
            const __nv_bfloat16* gAl = Xl + (long)(xrow0 + lrow) * EMBD + ko0 + lseg;
            const __nv_bfloat16* gBh = Wz  + (long)(col0 + lrow) * EMBD + ko0 + lseg;
            const __nv_bfloat16* gBl = Wzl + (long)(col0 + lrow) * EMBD + ko0 + lseg;
            char* sAh = smem + OFF_AH + lrow * (PADK * 2) + lseg * 2;
            char* sAl = smem + OFF_AL + lrow * (PADK * 2) + lseg * 2;
            char* sBh = smem + OFF_BH + lrow * (PADK * 2) + lseg * 2;
            char* sBl = smem + OFF_BL + lrow * (PADK * 2) + lseg * 2;
            #pragma unroll
            for (int j = 0; j < 4; j++) {
                *(uint4*)(sAh + j * 16) = *(const uint4*)(gAh + j * 8);
                *(uint4*)(sAl + j * 16) = *(const uint4*)(gAl + j * 8);
                *(uint4*)(sBh + j * 16) = *(const uint4*)(gBh + j * 8);
                *(uint4*)(sBl + j * 16) = *(const uint4*)(gBl + j * 8);
            }
        }
        __syncthreads();

        #pragma unroll
        for (int ks = 0; ks < 4; ks++) {
            const int ko = ks * 16;
            uint32_t ahf[2][4], alf[2][4];
            #pragma unroll
            for (int mt = 0; mt < 2; mt++) {
                const int r0 = wm * 32 + mt * 16 + g;
                const char* bAh = smem + OFF_AH;
                const char* bAl = smem + OFF_AL;
                const int c0 = (ko + 2 * tig) * 2;
                const int c8 = (ko + 8 + 2 * tig) * 2;
                ahf[mt][0] = *(const uint32_t*)(bAh + r0 * (PADK*2) + c0);
                ahf[mt][1] = *(const uint32_t*)(bAh + (r0+8) * (PADK*2) + c0);
                ahf[mt][2] = *(const uint32_t*)(bAh + r0 * (PADK*2) + c8);
                ahf[mt][3] = *(const uint32_t*)(bAh + (r0+8) * (PADK*2) + c8);
                alf[mt][0] = *(const uint32_t*)(bAl + r0 * (PADK*2) + c0);
                alf[mt][1] = *(const uint32_t*)(bAl + (r0+8) * (PADK*2) + c0);
                alf[mt][2] = *(const uint32_t*)(bAl + r0 * (PADK*2) + c8);
                alf[mt][3] = *(const uint32_t*)(bAl + (r0+8) * (PADK*2) + c8);
            }
            #pragma unroll
            for (int nt = 0; nt < 8; nt++) {
                const int nr = wn * 64 + nt * 8 + g;
                const char* bBh = smem + OFF_BH;
                const char* bBl = smem + OFF_BL;
                const int c0 = (ko + 2 * tig) * 2;
                const int c8 = (ko + 8 + 2 * tig) * 2;
                const uint32_t bh0 = *(const uint32_t*)(bBh + nr * (PADK*2) + c0);
                const uint32_t bh1 = *(const uint32_t*)(bBh + nr * (PADK*2) + c8);
                const uint32_t bl0 = *(const uint32_t*)(bBl + nr * (PADK*2) + c0);
                const uint32_t bl1 = *(const uint32_t*)(bBl + nr * (PADK*2) + c8);
                #pragma unroll
                for (int mt = 0; mt < 2; mt++) {
                    mma_bf16(acc[mt][nt], ahf[mt], bh0, bh1);
                    mma_bf16(acc[mt][nt], ahf[mt], bl0, bl1);
                    mma_bf16(acc[mt][nt], alf[mt], bh0, bh1);
                }
            }
        }
        __syncthreads();
    }

    #pragma unroll
    for (int mt = 0; mt < 2; mt++) {
        const int r_lo = crow0 + wm * 32 + mt * 16 + g;
        const int r_hi = r_lo + 8;
        #pragma unroll
        for (int nt = 0; nt < 8; nt++) {
            const int col = col0 + wn * 64 + nt * 8 + 2 * tig;
            if (r_lo < cvalid)
                *(float2*)(C + (long)r_lo * EMBD + col) =
                    make_float2(acc[mt][nt][0], acc[mt][nt][1]);
            if (r_hi < cvalid)
                *(float2*)(C + (long)r_hi * EMBD + col) =
                    make_float2(acc[mt][nt][2], acc[mt][nt][3]);
        }
    }
}

// =================== HMMA flash attention ==================================
// grid (H, B), block 128 (4 warps; warp w -> rows w*32..w*32+31 = 2 m16 tiles)
// S = Q@K^T via bf16-split mma (Q/K frags from fp32 global); P fragments feed
// P@V mma directly (C-layout == A-layout composition); V^T staged hi/lo in smem.
#define VTP 140   // padded token stride for Vt rows
__global__ void __launch_bounds__(128)
attn_kernel(const float* __restrict__ Q, const float* __restrict__ K,
            const float* __restrict__ V, float* __restrict__ O)
{
    __shared__ __nv_bfloat16 Vth[16][VTP];
    __shared__ __nv_bfloat16 Vtl[16][VTP];

    const int h = blockIdx.x;
    const int b = blockIdx.y;
    const int tid = threadIdx.x;
    const int lane = tid & 31;
    const int warp = tid >> 5;
    const int g = lane >> 2;
    const int tig = lane & 3;
    const int r0 = warp * 32;

    // Q fragments hi/lo (fp32 global -> split)
    uint32_t qh[2][4], ql[2][4];
    #pragma unroll
    for (int mt = 0; mt < 2; mt++) {
        const int rA = r0 + mt * 16 + g;
        const int rB = rA + 8;
        const float* qa = Q + ((long)b * MROWS + rA) * EMBD + h * DHEAD;
        const float* qb = Q + ((long)b * MROWS + rB) * EMBD + h * DHEAD;
        float2 x0 = *(const float2*)(qa + 2 * tig);
        float2 x1 = *(const float2*)(qb + 2 * tig);
        float2 x2 = *(const float2*)(qa + 8 + 2 * tig);
        float2 x3 = *(const float2*)(qb + 8 + 2 * tig);
        split2(x0.x, x0.y, qh[mt][0], ql[mt][0]);
        split2(x1.x, x1.y, qh[mt][1], ql[mt][1]);
        split2(x2.x, x2.y, qh[mt][2], ql[mt][2]);
        split2(x3.x, x3.y, qh[mt][3], ql[mt][3]);
    }

    float accO[2][2][4] = {};   // [mt][dn][c]
    float lsum[2][2] = {};      // [mt][row g / row g+8]

    #pragma unroll 1
    for (int c = 0; c < 4; c++) {
        const int t0 = c * 128;
        __syncthreads();
        // stage V^T hi/lo: thread (d = tid>>3, i = tid&7) handles 16 tokens
        {
            const int d = tid >> 3;
            const int i = tid & 7;
            const float* vp = V + ((long)b * TTOK + t0 + i * 16) * EMBD
                              + h * DHEAD + d;
            #pragma unroll
            for (int jj = 0; jj < 16; jj += 2) {
                const float v0 = vp[(long)jj * EMBD];
                const float v1 = vp[(long)(jj + 1) * EMBD];
                uint32_t hi, lo;
                split2(v0, v1, hi, lo);
                *(uint32_t*)&Vth[d][i * 16 + jj] = hi;
                *(uint32_t*)&Vtl[d][i * 16 + jj] = lo;
            }
        }
        __syncthreads();

        #pragma unroll 1
        for (int ntp = 0; ntp < 8; ntp++) {
            // K fragments for the two n-tiles of this k-step
            uint32_t kh[2][2], kl[2][2];
            #pragma unroll
            for (int half = 0; half < 2; half++) {
                const int tok = t0 + (2 * ntp + half) * 8 + g;
                const float* kp = K + ((long)b * TTOK + tok) * EMBD + h * DHEAD;
                float2 y0 = *(const float2*)(kp + 2 * tig);
                float2 y1 = *(const float2*)(kp + 8 + 2 * tig);
                split2(y0.x, y0.y, kh[half][0], kl[half][0]);
                split2(y1.x, y1.y, kh[half][1], kl[half][1]);
            }
            #pragma unroll
            for (int mt = 0; mt < 2; mt++) {
                uint32_t ph[4], pl[4];
                #pragma unroll
                for (int half = 0; half < 2; half++) {
                    float s[4] = {0.f, 0.f, 0.f, 0.f};
                    mma_bf16(s, qh[mt], kh[half][0], kh[half][1]);
                    mma_bf16(s, qh[mt], kl[half][0], kl[half][1]);
                    mma_bf16(s, ql[mt], kh[half][0], kh[half][1]);
                    const float p0 = __expf(s[0] * 0.25f);
                    const float p1 = __expf(s[1] * 0.25f);
                    const float p2 = __expf(s[2] * 0.25f);
                    const float p3 = __expf(s[3] * 0.25f);
                    lsum[mt][0] += p0 + p1;
                    lsum[mt][1] += p2 + p3;
                    split2(p0, p1, ph[half * 2 + 0], pl[half * 2 + 0]);
                    split2(p2, p3, ph[half * 2 + 1], pl[half * 2 + 1]);
                }
                // reorder to a-frag: a0=row g k0-1, a1=row g+8 k0-1, a2=row g k8-9, a3=row g+8 k8-9
                uint32_t pah[4] = {ph[0], ph[1], ph[2], ph[3]};
                uint32_t pal[4] = {pl[0], pl[1], pl[2], pl[3]};
                #pragma unroll
                for (int dn = 0; dn < 2; dn++) {
                    const int vr = 8 * dn + g;
                    const uint32_t vh0 = *(const uint32_t*)&Vth[vr][ntp * 16 + 2 * tig];
                    const uint32_t vh1 = *(const uint32_t*)&Vth[vr][ntp * 16 + 8 + 2 * tig];
                    const uint32_t vl0 = *(const uint32_t*)&Vtl[vr][ntp * 16 + 2 * tig];
                    const uint32_t vl1 = *(const uint32_t*)&Vtl[vr][ntp * 16 + 8 + 2 * tig];
                    mma_bf16(accO[mt][dn], pah, vh0, vh1);
                    mma_bf16(accO[mt][dn], pah, vl0, vl1);
                    mma_bf16(accO[mt][dn], pal, vh0, vh1);
                }
            }
        }
    }

    // reduce lsum across the tig quad (lanes g*4 + tig)
    #pragma unroll
    for (int mt = 0; mt < 2; mt++) {
        #pragma unroll
        for (int j = 0; j < 2; j++) {
            float v = lsum[mt][j];
            v += __shfl_xor_sync(0xFFFFFFFFu, v, 1);
            v += __shfl_xor_sync(0xFFFFFFFFu, v, 2);
            lsum[mt][j] = v;
        }
    }

    // tail token t = 512 (fp32 exact)
    {
        const float* kp = K + ((long)b * TTOK + 512) * EMBD + h * DHEAD;
        const float2 k0 = *(const float2*)(kp + 2 * tig);
        const float2 k1 = *(const float2*)(kp + 8 + 2 * tig);
        const float* vp = V + ((long)b * TTOK + 512) * EMBD + h * DHEAD;
        #pragma unroll
        for (int mt = 0; mt < 2; mt++) {
            const int rA = r0 + mt * 16 + g;
            const int rB = rA + 8;
            const float* qa = Q + ((long)b * MROWS + rA) * EMBD + h * DHEAD;
            const float* qb = Q + ((long)b * MROWS + rB) * EMBD + h * DHEAD;
            const float2 qa0 = *(const float2*)(qa + 2 * tig);
            const float2 qa1 = *(const float2*)(qa + 8 + 2 * tig);
            const float2 qb0 = *(const float2*)(qb + 2 * tig);
            const float2 qb1 = *(const float2*)(qb + 8 + 2 * tig);
            float dA = qa0.x * k0.x + qa0.y * k0.y + qa1.x * k1.x + qa1.y * k1.y;
            float dB = qb0.x * k0.x + qb0.y * k0.y + qb1.x * k1.x + qb1.y * k1.y;
            dA += __shfl_xor_sync(0xFFFFFFFFu, dA, 1);
            dA += __shfl_xor_sync(0xFFFFFFFFu, dA, 2);
            dB += __shfl_xor_sync(0xFFFFFFFFu, dB, 1);
            dB += __shfl_xor_sync(0xFFFFFFFFu, dB, 2);
            const float pA = __expf(dA * 0.25f);
            const float pB = __expf(dB * 0.25f);
            lsum[mt][0] += pA;
            lsum[mt][1] += pB;
            #pragma unroll
            for (int dn = 0; dn < 2; dn++) {
                const float2 v = *(const float2*)(vp + dn * 8 + 2 * tig);
                accO[mt][dn][0] += pA * v.x;
                accO[mt][dn][1] += pA * v.y;
                accO[mt][dn][2] += pB * v.x;
                accO[mt][dn][3] += pB * v.y;
            }
        }
    }

    // normalize + write
    #pragma unroll
    for (int mt = 0; mt < 2; mt++) {
        const int rA = r0 + mt * 16 + g;
        const int rB = rA + 8;
        const float invA = 1.0f / lsum[mt][0];
        const float invB = 1.0f / lsum[mt][1];
        float* oa = O + ((long)b * MROWS + rA) * EMBD + h * DHEAD;
        float* ob = O + ((long)b * MROWS + rB) * EMBD + h * DHEAD;
        #pragma unroll
        for (int dn = 0; dn < 2; dn++) {
            *(float2*)(oa + dn * 8 + 2 * tig) =
                make_float2(accO[mt][dn][0] * invA, accO[mt][dn][1] * invA);
            *(float2*)(ob + dn * 8 + 2 * tig) =
                make_float2(accO[mt][dn][2] * invB, accO[mt][dn][3] * invB);
        }
    }
}

// =================== Wc projection (+bias), 64x128 tiles ====================
#define BK 16
#define BN 128
#define WBM 64
__global__ void __launch_bounds__(256)
wc_kernel(const float* __restrict__ X, const float* __restrict__ W,
          const float* __restrict__ bias, float* __restrict__ C)
{
    __shared__ float As[2][BK][WBM + 4];
    __shared__ float Bs[2][BK][BN];

    const int tid  = threadIdx.x;
    const int row0 = blockIdx.y * WBM;
    const int col0 = blockIdx.x * BN;

    const int a_row = tid >> 2;
    const int a_k   = (tid & 3) * 4;
    const int b_k   = tid >> 4;
    const int b_n   = (tid & 15) * 8;
    const int tx = tid & 15;
    const int ty = tid >> 4;

    const float* xrow = X + (long)(row0 + a_row) * EMBD;
    const float* wptr = W + (long)b_k * EMBD + col0 + b_n;

    float4 av, bv0, bv1;
    av  = *(const float4*)(xrow + a_k);
    bv0 = *(const float4*)(wptr);
    bv1 = *(const float4*)(wptr + 4);
    As[0][a_k+0][a_row]=av.x; As[0][a_k+1][a_row]=av.y;
    As[0][a_k+2][a_row]=av.z; As[0][a_k+3][a_row]=av.w;
    *(float4*)&Bs[0][b_k][b_n]     = bv0;
    *(float4*)&Bs[0][b_k][b_n + 4] = bv1;
    __syncthreads();

    ull acc2[4][4] = {};

    #pragma unroll 1
    for (int ks = 0; ks < EMBD / BK; ks++) {
        const int cur = ks & 1;
        const bool has_next = (ks < EMBD / BK - 1);
        if (has_next) {
            const int k0 = (ks + 1) * BK;
            av  = *(const float4*)(xrow + k0 + a_k);
            bv0 = *(const float4*)(wptr + (long)k0 * EMBD);
            bv1 = *(const float4*)(wptr + (long)k0 * EMBD + 4);
        }
        #pragma unroll
        for (int kk = 0; kk < BK; kk++) {
            float4 a0 = *(const float4*)&As[cur][kk][ty * 4];
            ulonglong2 p0 = *(const ulonglong2*)&Bs[cur][kk][tx * 4];
            ulonglong2 p1 = *(const ulonglong2*)&Bs[cur][kk][64 + tx * 4];
            ull B2[4] = {p0.x, p0.y, p1.x, p1.y};
            float a[4] = {a0.x, a0.y, a0.z, a0.w};
            #pragma unroll
            for (int i = 0; i < 4; i++) {
                const ull ai = bcast2(a[i]);
                #pragma unroll
                for (int j = 0; j < 4; j++)
                    acc2[i][j] = fma2(ai, B2[j], acc2[i][j]);
            }
        }
        if (has_next) {
            const int nxt = 1 - cur;
            As[nxt][a_k+0][a_row]=av.x; As[nxt][a_k+1][a_row]=av.y;
            As[nxt][a_k+2][a_row]=av.z; As[nxt][a_k+3][a_row]=av.w;
            *(float4*)&Bs[nxt][b_k][b_n]     = bv0;
            *(float4*)&Bs[nxt][b_k][b_n + 4] = bv1;
        }
        __syncthreads();
    }

    float4 bb0 = *(const float4*)(bias + col0 + tx * 4);
    float4 bb1 = *(const float4*)(bias + col0 + 64 + tx * 4);

    #pragma unroll
    for (int i = 0; i < 4; i++) {
        const int r = row0 + ty * 4 + i;
        float2 c0 = unpack2(acc2[i][0]);
        float2 c1 = unpack2(acc2[i][1]);
        float2 c2 = unpack2(acc2[i][2]);
        float2 c3 = unpack2(acc2[i][3]);
        float4 o0 = make_float4(c0.x+bb0.x, c0.y+bb0.y, c1.x+bb0.z, c1.y+bb0.w);
        float4 o1 = make_float4(c2.x+bb1.x, c2.y+bb1.y, c3.x+bb1.z, c3.y+bb1.w);
        *(float4*)(C + (long)r * EMBD + col0 + tx * 4)      = o0;
        *(float4*)(C + (long)r * EMBD + col0 + 64 + tx * 4) = o1;
    }
}

// =================== score2: 4 full col tiles, scalar epilogue =============
#define BM 128
#define ASTRIDE (BM + 4)
#define GEMM_MICRO(cur)                                                        \
    _Pragma("unroll")                                                          \
    for (int kk = 0; kk < BK; kk++) {                                          \
        float4 a0 = *(const float4*)&As[cur][kk][ty * 4];                      \
        float4 a1 = *(const float4*)&As[cur][kk][64 + ty * 4];                 \
        ulonglong2 p0 = *(const ulonglong2*)&Bs[cur][kk][tx * 4];              \
        ulonglong2 p1 = *(const ulonglong2*)&Bs[cur][kk][64 + tx * 4];         \
        ull B2[4] = {p0.x, p0.y, p1.x, p1.y};                                  \
        float a[8] = {a0.x,a0.y,a0.z,a0.w,a1.x,a1.y,a1.z,a1.w};                \
        _Pragma("unroll")                                                      \
        for (int i = 0; i < 8; i++) {                                          \
            const ull ai = bcast2(a[i]);                                       \
            _Pragma("unroll")                                                  \
            for (int j = 0; j < 4; j++)                                        \
                acc2[i][j] = fma2(ai, B2[j], acc2[i][j]);                      \
        }                                                                      \
    }

__global__ void __launch_bounds__(256, 2)
score2_kernel(const float* __restrict__ MH, const float* __restrict__ jobs,
              const float* __restrict__ skip, const float* __restrict__ mask,
              float* __restrict__ out, float* __restrict__ sums)
{
    __shared__ float As[2][BK][ASTRIDE];
    __shared__ float Bs[2][BK][BN + 4];
    __shared__ float red[256];

    const int tid  = threadIdx.x;
    const int b    = blockIdx.z;
    const int col0 = blockIdx.x * BN;

    const int a_row = tid >> 1;
    const int a_k   = (tid & 1) * 8;
    const int tx = tid & 15;
    const int ty = tid >> 4;

    const float* arow = MH + ((long)b * MROWS + a_row) * EMBD;
    const int t_l = tid >> 1;
    const float* brow = jobs_row(jobs, skip, b, col0 + t_l);

    float4 av0, av1, bv0, bv1;
    av0 = *(const float4*)(arow + a_k);
    av1 = *(const float4*)(arow + a_k + 4);
    bv0 = *(const float4*)(brow + a_k);
    bv1 = *(const float4*)(brow + a_k + 4);
    As[0][a_k+0][a_row]=av0.x; As[0][a_k+1][a_row]=av0.y;
    As[0][a_k+2][a_row]=av0.z; As[0][a_k+3][a_row]=av0.w;
    As[0][a_k+4][a_row]=av1.x; As[0][a_k+5][a_row]=av1.y;
    As[0][a_k+6][a_row]=av1.z; As[0][a_k+7][a_row]=av1.w;
    Bs[0][a_k+0][t_l]=bv0.x; Bs[0][a_k+1][t_l]=bv0.y;
    Bs[0][a_k+2][t_l]=bv0.z; Bs[0][a_k+3][t_l]=bv0.w;
    Bs[0][a_k+4][t_l]=bv1.x; Bs[0][a_k+5][t_l]=bv1.y;
    Bs[0][a_k+6][t_l]=bv1.z; Bs[0][a_k+7][t_l]=bv1.w;
    __syncthreads();

    ull acc2[8][4] = {};

    #pragma unroll 1
    for (int ks = 0; ks < EMBD / BK; ks++) {
        const int cur = ks & 1;
        const bool has_next = (ks < EMBD / BK - 1);
        if (has_next) {
            const int k0 = (ks + 1) * BK;
            av0 = *(const float4*)(arow + k0 + a_k);
            av1 = *(const float4*)(arow + k0 + a_k + 4);
            bv0 = *(const float4*)(brow + k0 + a_k);
            bv1 = *(const float4*)(brow + k0 + a_k + 4);
        }
        GEMM_MICRO(cur)
        if (has_next) {
            const int nxt = 1 - cur;
            As[nxt][a_k+0][a_row]=av0.x; As[nxt][a_k+1][a_row]=av0.y;
            As[nxt][a_k+2][a_row]=av0.z; As[nxt][a_k+3][a_row]=av0.w;
            As[nxt][a_k+4][a_row]=av1.x; As[nxt][a_k+5][a_row]=av1.y;
            As[nxt][a_k+6][a_row]=av1.z; As[nxt][a_k+7][a_row]=av1.w;
            Bs[nxt][a_k+0][t_l]=bv0.x; Bs[nxt][a_k+1][t_l]=bv0.y;
            Bs[nxt][a_k+2][t_l]=bv0.z; Bs[nxt][a_k+3][t_l]=bv0.w;
            Bs[nxt][a_k+4][t_l]=bv1.x; Bs[nxt][a_k+5][t_l]=bv1.y;
            Bs[nxt][a_k+6][t_l]=bv1.z; Bs[nxt][a_k+7][t_l]=bv1.w;
        }
        __syncthreads();
    }

    float lsum = 0.0f;
    #pragma unroll
    for (int half = 0; half < 2; half++) {
        #pragma unroll
        for (int i = 0; i < 4; i++) {
            const int m = half * 64 + ty * 4 + i;
            const int ai = half * 4 + i;
            const long rowbase = (long)b * OUT_PER_B + (long)m * TTOK;
            #pragma unroll
            for (int jh = 0; jh < 2; jh++) {
                const int t = col0 + jh * 64 + tx * 4;
                float2 v0 = unpack2(acc2[ai][jh * 2 + 0]);
                float2 v1 = unpack2(acc2[ai][jh * 2 + 1]);
                float vv[4] = {v0.x, v0.y, v1.x, v1.y};
                #pragma unroll
                for (int e = 0; e < 4; e++) {
                    const long li = rowbase + t + e;
                    const float y = __expf(10.0f * tanh_fast(vv[e] * 0.0625f) + mask[li]);
                    out[li] = y;
                    lsum += y;
                }
            }
        }
    }

    red[tid] = lsum;
    __syncthreads();
    #pragma unroll
    for (int s = 128; s > 0; s >>= 1) {
        if (tid < s) red[tid] += red[tid + s];
        __syncthreads();
    }
    if (tid == 0) atomicAdd(&sums[b], red[0]);
}

// =================== t=512 column tail ================
__global__ void __launch_bounds__(128)
tail_kernel(const float* __restrict__ MH, const float* __restrict__ jobs,
            const float* __restrict__ mask, float* __restrict__ out,
            float* __restrict__ sums)
{
    __shared__ float jrow[EMBD];
    __shared__ float red[128];

    const int b = blockIdx.x;
    const int m = threadIdx.x;

    const float* jr = jobs + ((long)b * JJOBS + 511) * EMBD;
    *(float2*)&jrow[m * 2] = *(const float2*)(jr + m * 2);
    __syncthreads();

    const float* mh = MH + ((long)b * MROWS + m) * EMBD;
    ull d2 = bcast2(0.0f);
    #pragma unroll
    for (int k = 0; k < EMBD; k += 8) {
        ulonglong2 a = *(const ulonglong2*)(mh + k);
        ulonglong2 a2 = *(const ulonglong2*)(mh + k + 4);
        ulonglong2 w = *(const ulonglong2*)&jrow[k];
        ulonglong2 w2 = *(const ulonglong2*)&jrow[k + 4];
        d2 = fma2(a.x, w.x, d2);
        d2 = fma2(a.y, w.y, d2);
        d2 = fma2(a2.x, w2.x, d2);
        d2 = fma2(a2.y, w2.y, d2);
    }
    float2 f = unpack2(d2);
    const float sc = (f.x + f.y) * 0.0625f;
    const long li = (long)b * OUT_PER_B + (long)m * TTOK + 512;
    const float y = __expf(10.0f * tanh_fast(sc) + mask[li]);
    out[li] = y;

    red[m] = y;
    __syncthreads();
    #pragma unroll
    for (int s = 64; s > 0; s >>= 1) {
        if (m < s) red[m] += red[m + s];
        __syncthreads();
    }
    if (m == 0) atomicAdd(&sums[b], red[0]);
}

// =================== normalize =======================
__global__ void __launch_bounds__(256)
norm_kernel(float4* __restrict__ out, const float* __restrict__ sums)
{
    const int b = blockIdx.y;
    const long per_b4 = OUT_PER_B / 4;
    const long idx = (long)blockIdx.x * blockDim.x + threadIdx.x;
    if (idx < per_b4) {
        const float inv = 1.0f / sums[b];
        float4 v = out[(long)b * per_b4 + idx];
        v.x *= inv; v.y *= inv; v.z *= inv; v.w *= inv;
        out[(long)b * per_b4 + idx] = v;
    }
}

// =================== launch ===================
extern "C" void kernel_launch(void* const* d_in, const int* in_sizes, int n_in,
                              void* d_out, int out_size)
{
    const float* machine = (const float*)d_in[0];
    const float* jobs    = (const float*)d_in[1];
    const float* mask    = (const float*)d_in[2];
    const float* Wq3     = (const float*)d_in[3];
    const float* Wk      = (const float*)d_in[4];
    const float* Wv      = (const float*)d_in[5];
    const float* Wc      = (const float*)d_in[6];
    const float* bc      = (const float*)d_in[7];
    const float* skip    = (const float*)d_in[8];
    float* out = (float*)d_out;

    float *Qp, *Kp, *Vp, *Op, *MHp, *Sp;
    __nv_bfloat16 *Xh, *Xl, *Wh, *Wl;
    cudaGetSymbolAddress((void**)&Qp,  g_Q);
    cudaGetSymbolAddress((void**)&Kp,  g_K);
    cudaGetSymbolAddress((void**)&Vp,  g_V);
    cudaGetSymbolAddress((void**)&Op,  g_O);
    cudaGetSymbolAddress((void**)&MHp, g_MH);
    cudaGetSymbolAddress((void**)&Sp,  g_SUM);
    cudaGetSymbolAddress((void**)&Xh,  g_Xh);
    cudaGetSymbolAddress((void**)&Xl,  g_Xl);
    cudaGetSymbolAddress((void**)&Wh,  g_Wh);
    cudaGetSymbolAddress((void**)&Wl,  g_Wl);

    cudaFuncSetAttribute(proj_wmma_kernel,
                         cudaFuncAttributeMaxDynamicSharedMemorySize, PROJ_SMEM);

    convert_w_kernel<<<dim3(8, 8, 3), 256>>>(Wk, Wv, Wq3, Wh, Wl);
    {
        const long total = (long)XROWS * 32;
        convert_x_kernel<<<(int)((total + 255) / 256), 256>>>(
            jobs, skip, machine, Xh, Xl, Sp);
    }

    proj_wmma_kernel<<<dim3(2, 257, 3), 256, PROJ_SMEM>>>(
        Xh, Xl, Wh, Wl, Kp, Vp, Qp);

    attn_kernel<<<dim3(HEADS, BATCH), 128>>>(Qp, Kp, Vp, Op);

    wc_kernel<<<dim3(EMBD / BN, (BATCH * MROWS) / WBM), 256>>>(Op, Wc, bc, MHp);

    score2_kernel<<<dim3(4, 1, BATCH), 256>>>(MHp, jobs, skip, mask, out, Sp);
    tail_kernel<<<BATCH, 128>>>(MHp, jobs, mask, out, Sp);

    const int per_b4 = OUT_PER_B / 4;
    norm_kernel<<<dim3((per_b4 + 255) / 256, BATCH), 256>>>((float4*)out, Sp);
}

// round 15
// speedup vs baseline: 1.6313x; 1.1331x over previous
#include <cuda_runtime.h>
#include <cuda_bf16.h>
#include <math.h>
#include <stdint.h>

#define EMBD   256
#define HEADS  16
#define DHEAD  16
#define BATCH  64
#define MROWS  128
#define JJOBS  512
#define TTOK   513
#define OUT_PER_B (MROWS * TTOK)   // 65664

#define XJOBS   32832
#define XMACH0  32896
#define XROWS   41088

typedef unsigned long long ull;

__device__ float g_Q [BATCH * MROWS * EMBD];
__device__ float g_K [BATCH * TTOK  * EMBD];
__device__ float g_V [BATCH * TTOK  * EMBD];
__device__ float g_O [BATCH * MROWS * EMBD];
__device__ float g_MH[BATCH * MROWS * EMBD];
__device__ float g_SUM[BATCH];
__device__ __nv_bfloat16 g_Xh[(long)XROWS * EMBD];
__device__ __nv_bfloat16 g_Xl[(long)XROWS * EMBD];
__device__ __nv_bfloat16 g_Wh[3 * EMBD * EMBD];   // [z][n][k]
__device__ __nv_bfloat16 g_Wl[3 * EMBD * EMBD];
__device__ __nv_bfloat16 g_MHh[BATCH * MROWS * EMBD];
__device__ __nv_bfloat16 g_MHl[BATCH * MROWS * EMBD];

// ---------------- packed f32x2 helpers ----------------
__device__ __forceinline__ ull fma2(ull a, ull b, ull c) {
    ull d; asm("fma.rn.f32x2 %0, %1, %2, %3;" : "=l"(d) : "l"(a), "l"(b), "l"(c));
    return d;
}
__device__ __forceinline__ ull bcast2(float x) {
    ull d; asm("mov.b64 %0, {%1, %2};" : "=l"(d) : "f"(x), "f"(x));
    return d;
}
__device__ __forceinline__ float2 unpack2(ull v) {
    float2 f; asm("mov.b64 {%0, %1}, %2;" : "=f"(f.x), "=f"(f.y) : "l"(v));
    return f;
}
__device__ __forceinline__ float tanh_fast(float x) {
    const float e = __expf(2.0f * x);
    return 1.0f - __fdividef(2.0f, e + 1.0f);
}

__device__ __forceinline__ const float* jobs_row(const float* __restrict__ jobs,
                                                 const float* __restrict__ skip,
                                                 int b, int t) {
    return (t == 0) ? skip : jobs + ((long)b * JJOBS + (t - 1)) * EMBD;
}

// mma.sync m16n8k16 row.col bf16 -> f32
__device__ __forceinline__ void mma_bf16(float* c, const uint32_t* a,
                                         uint32_t b0, uint32_t b1) {
    asm volatile(
        "mma.sync.aligned.m16n8k16.row.col.f32.bf16.bf16.f32 "
        "{%0,%1,%2,%3}, {%4,%5,%6,%7}, {%8,%9}, {%0,%1,%2,%3};"
        : "+f"(c[0]), "+f"(c[1]), "+f"(c[2]), "+f"(c[3])
        : "r"(a[0]), "r"(a[1]), "r"(a[2]), "r"(a[3]), "r"(b0), "r"(b1));
}

__device__ __forceinline__ uint32_t packbf(__nv_bfloat16 a, __nv_bfloat16 b) {
    __nv_bfloat162 t; t.x = a; t.y = b;
    return *(uint32_t*)&t;
}
__device__ __forceinline__ void split2(float x, float y,
                                       uint32_t& hi, uint32_t& lo) {
    const __nv_bfloat16 hx = __float2bfloat16_rn(x);
    const __nv_bfloat16 hy = __float2bfloat16_rn(y);
    const __nv_bfloat16 lx = __float2bfloat16_rn(x - __bfloat162float(hx));
    const __nv_bfloat16 ly = __float2bfloat16_rn(y - __bfloat162float(hy));
    hi = packbf(hx, hy);
    lo = packbf(lx, ly);
}

// =================== convert W -> bf16 hi/lo, transposed to [N][K] =========
__global__ void __launch_bounds__(256)
convert_w_kernel(const float* __restrict__ Wk, const float* __restrict__ Wv,
                 const float* __restrict__ Wq,
                 __nv_bfloat16* __restrict__ Wh, __nv_bfloat16* __restrict__ Wl)
{
    __shared__ float tile[32][33];
    const int z = blockIdx.z;
    const float* W = (z == 0) ? Wk : (z == 1) ? Wv : Wq;
    const int kb = blockIdx.y * 32;
    const int nb = blockIdx.x * 32;
    const int tx = threadIdx.x & 31;
    const int ty = threadIdx.x >> 5;

    #pragma unroll
    for (int i = 0; i < 32; i += 8)
        tile[ty + i][tx] = W[(long)(kb + ty + i) * EMBD + nb + tx];
    __syncthreads();
    #pragma unroll
    for (int i = 0; i < 32; i += 8) {
        const int n = nb + ty + i;
        const int k = kb + tx;
        const float w = tile[tx][ty + i];
        const __nv_bfloat16 hi = __float2bfloat16_rn(w);
        const __nv_bfloat16 lo = __float2bfloat16_rn(w - __bfloat162float(hi));
        const long idx = (long)z * EMBD * EMBD + (long)n * EMBD + k;
        Wh[idx] = hi;
        Wl[idx] = lo;
    }
}

// =================== convert X -> bf16 hi/lo ======
__global__ void __launch_bounds__(256)
convert_x_kernel(const float* __restrict__ jobs, const float* __restrict__ skip,
                 const float* __restrict__ machine,
                 __nv_bfloat16* __restrict__ Xh, __nv_bfloat16* __restrict__ Xl,
                 float* __restrict__ sums)
{
    if (blockIdx.x == 0 && threadIdx.x < BATCH) sums[threadIdx.x] = 0.0f;

    const long gid = (long)blockIdx.x * 256 + threadIdx.x;
    const long total = (long)XROWS * 32;
    if (gid >= total) return;
    const int row = (int)(gid >> 5);
    const int seg = ((int)gid & 31) * 8;

    float v[8] = {};
    const float* src = nullptr;
    if (row < XJOBS) {
        const int b = row / TTOK;
        const int t = row - b * TTOK;
        src = jobs_row(jobs, skip, b, t);
    } else if (row >= XMACH0) {
        src = machine + (long)(row - XMACH0) * EMBD;
    }
    if (src) {
        float4 a = *(const float4*)(src + seg);
        float4 c = *(const float4*)(src + seg + 4);
        v[0]=a.x; v[1]=a.y; v[2]=a.z; v[3]=a.w;
        v[4]=c.x; v[5]=c.y; v[6]=c.z; v[7]=c.w;
    }
    __nv_bfloat16 h[8], l[8];
    #pragma unroll
    for (int i = 0; i < 8; i++) {
        h[i] = __float2bfloat16_rn(v[i]);
        l[i] = __float2bfloat16_rn(v[i] - __bfloat162float(h[i]));
    }
    const long o = (long)row * EMBD + seg;
    *(uint4*)(Xh + o) = *(const uint4*)h;
    *(uint4*)(Xl + o) = *(const uint4*)l;
}

// =================== HMMA projection GEMM ==================================
#define PADK   72
#define TILE_B (128 * PADK * 2)
#define OFF_AH 0
#define OFF_AL (TILE_B)
#define OFF_BH (2 * TILE_B)
#define OFF_BL (3 * TILE_B)
#define PROJ_SMEM (4 * TILE_B)

__global__ void __launch_bounds__(256, 2)
proj_wmma_kernel(const __nv_bfloat16* __restrict__ Xh,
                 const __nv_bfloat16* __restrict__ Xl,
                 const __nv_bfloat16* __restrict__ Wh,
                 const __nv_bfloat16* __restrict__ Wl,
                 float* __restrict__ Kout, float* __restrict__ Vout,
                 float* __restrict__ Qout)
{
    extern __shared__ char smem[];
    const int z = blockIdx.z;
    const int row_tiles = (z == 2) ? 64 : 257;
    if ((int)blockIdx.y >= row_tiles) return;

    const int tid  = threadIdx.x;
    const int warp = tid >> 5;
    const int lane = tid & 31;
    const int wm = warp & 3;
    const int wn = warp >> 2;
    const int g   = lane >> 2;
    const int tig = lane & 3;

    const int xrow0 = blockIdx.y * 128 + ((z == 2) ? XMACH0 : 0);
    const int col0  = blockIdx.x * 128;
    const int crow0 = blockIdx.y * 128;
    const int cvalid = (z == 2) ? (BATCH * MROWS) : XJOBS;
    float* C = (z == 0) ? Kout : (z == 1) ? Vout : Qout;

    const __nv_bfloat16* Wz = Wh + (long)z * EMBD * EMBD;
    const __nv_bfloat16* Wzl = Wl + (long)z * EMBD * EMBD;

    const int lrow = tid >> 1;
    const int lseg = (tid & 1) * 32;

    float acc[2][8][4] = {};

    #pragma unroll 1
    for (int kc = 0; kc < 4; kc++) {
        const int ko0 = kc * 64;
        {
            const __nv_bfloat16* gAh = Xh + (long)(xrow0 + lrow) * EMBD + ko0 + lseg;
            const __nv_bfloat16* gAl = Xl + (long)(xrow0 + lrow) * EMBD + ko0 + lseg;
            const __nv_bfloat16* gBh = Wz  + (long)(col0 + lrow) * EMBD + ko0 + lseg;
            const __nv_bfloat16* gBl = Wzl + (long)(col0 + lrow) * EMBD + ko0 + lseg;
            char* sAh = smem + OFF_AH + lrow * (PADK * 2) + lseg * 2;
            char* sAl = smem + OFF_AL + lrow * (PADK * 2) + lseg * 2;
            char* sBh = smem + OFF_BH + lrow * (PADK * 2) + lseg * 2;
            char* sBl = smem + OFF_BL + lrow * (PADK * 2) + lseg * 2;
            #pragma unroll
            for (int j = 0; j < 4; j++) {
                *(uint4*)(sAh + j * 16) = *(const uint4*)(gAh + j * 8);
                *(uint4*)(sAl + j * 16) = *(const uint4*)(gAl + j * 8);
                *(uint4*)(sBh + j * 16) = *(const uint4*)(gBh + j * 8);
                *(uint4*)(sBl + j * 16) = *(const uint4*)(gBl + j * 8);
            }
        }
        __syncthreads();

        #pragma unroll
        for (int ks = 0; ks < 4; ks++) {
            const int ko = ks * 16;
            uint32_t ahf[2][4], alf[2][4];
            #pragma unroll
            for (int mt = 0; mt < 2; mt++) {
                const int r0 = wm * 32 + mt * 16 + g;
                const char* bAh = smem + OFF_AH;
                const char* bAl = smem + OFF_AL;
                const int c0 = (ko + 2 * tig) * 2;
                const int c8 = (ko + 8 + 2 * tig) * 2;
                ahf[mt][0] = *(const uint32_t*)(bAh + r0 * (PADK*2) + c0);
                ahf[mt][1] = *(const uint32_t*)(bAh + (r0+8) * (PADK*2) + c0);
                ahf[mt][2] = *(const uint32_t*)(bAh + r0 * (PADK*2) + c8);
                ahf[mt][3] = *(const uint32_t*)(bAh + (r0+8) * (PADK*2) + c8);
                alf[mt][0] = *(const uint32_t*)(bAl + r0 * (PADK*2) + c0);
                alf[mt][1] = *(const uint32_t*)(bAl + (r0+8) * (PADK*2) + c0);
                alf[mt][2] = *(const uint32_t*)(bAl + r0 * (PADK*2) + c8);
                alf[mt][3] = *(const uint32_t*)(bAl + (r0+8) * (PADK*2) + c8);
            }
            #pragma unroll
            for (int nt = 0; nt < 8; nt++) {
                const int nr = wn * 64 + nt * 8 + g;
                const char* bBh = smem + OFF_BH;
                const char* bBl = smem + OFF_BL;
                const int c0 = (ko + 2 * tig) * 2;
                const int c8 = (ko + 8 + 2 * tig) * 2;
                const uint32_t bh0 = *(const uint32_t*)(bBh + nr * (PADK*2) + c0);
                const uint32_t bh1 = *(const uint32_t*)(bBh + nr * (PADK*2) + c8);
                const uint32_t bl0 = *(const uint32_t*)(bBl + nr * (PADK*2) + c0);
                const uint32_t bl1 = *(const uint32_t*)(bBl + nr * (PADK*2) + c8);
                #pragma unroll
                for (int mt = 0; mt < 2; mt++) {
                    mma_bf16(acc[mt][nt], ahf[mt], bh0, bh1);
                    mma_bf16(acc[mt][nt], ahf[mt], bl0, bl1);
                    mma_bf16(acc[mt][nt], alf[mt], bh0, bh1);
                }
            }
        }
        __syncthreads();
    }

    #pragma unroll
    for (int mt = 0; mt < 2; mt++) {
        const int r_lo = crow0 + wm * 32 + mt * 16 + g;
        const int r_hi = r_lo + 8;
        #pragma unroll
        for (int nt = 0; nt < 8; nt++) {
            const int col = col0 + wn * 64 + nt * 8 + 2 * tig;
            if (r_lo < cvalid)
                *(float2*)(C + (long)r_lo * EMBD + col) =
                    make_float2(acc[mt][nt][0], acc[mt][nt][1]);
            if (r_hi < cvalid)
                *(float2*)(C + (long)r_hi * EMBD + col) =
                    make_float2(acc[mt][nt][2], acc[mt][nt][3]);
        }
    }
}

// =================== HMMA flash attention (K staged in smem) ===============
#define VTP 140
#define KPAD 18
__global__ void __launch_bounds__(128)
attn_kernel(const float* __restrict__ Q, const float* __restrict__ K,
            const float* __restrict__ V, float* __restrict__ O)
{
    __shared__ __nv_bfloat16 Vth[16][VTP];
    __shared__ __nv_bfloat16 Vtl[16][VTP];
    __shared__ __nv_bfloat16 Ksh[128][KPAD];
    __shared__ __nv_bfloat16 Ksl[128][KPAD];

    const int h = blockIdx.x;
    const int b = blockIdx.y;
    const int tid = threadIdx.x;
    const int lane = tid & 31;
    const int warp = tid >> 5;
    const int g = lane >> 2;
    const int tig = lane & 3;
    const int r0 = warp * 32;

    uint32_t qh[2][4], ql[2][4];
    #pragma unroll
    for (int mt = 0; mt < 2; mt++) {
        const int rA = r0 + mt * 16 + g;
        const int rB = rA + 8;
        const float* qa = Q + ((long)b * MROWS + rA) * EMBD + h * DHEAD;
        const float* qb = Q + ((long)b * MROWS + rB) * EMBD + h * DHEAD;
        float2 x0 = *(const float2*)(qa + 2 * tig);
        float2 x1 = *(const float2*)(qb + 2 * tig);
        float2 x2 = *(const float2*)(qa + 8 + 2 * tig);
        float2 x3 = *(const float2*)(qb + 8 + 2 * tig);
        split2(x0.x, x0.y, qh[mt][0], ql[mt][0]);
        split2(x1.x, x1.y, qh[mt][1], ql[mt][1]);
        split2(x2.x, x2.y, qh[mt][2], ql[mt][2]);
        split2(x3.x, x3.y, qh[mt][3], ql[mt][3]);
    }

    float accO[2][2][4] = {};
    float lsum[2][2] = {};

    #pragma unroll 1
    for (int c = 0; c < 4; c++) {
        const int t0 = c * 128;
        __syncthreads();
        // stage V^T hi/lo
        {
            const int d = tid >> 3;
            const int i = tid & 7;
            const float* vp = V + ((long)b * TTOK + t0 + i * 16) * EMBD
                              + h * DHEAD + d;
            #pragma unroll
            for (int jj = 0; jj < 16; jj += 2) {
                const float v0 = vp[(long)jj * EMBD];
                const float v1 = vp[(long)(jj + 1) * EMBD];
                uint32_t hi, lo;
                split2(v0, v1, hi, lo);
                *(uint32_t*)&Vth[d][i * 16 + jj] = hi;
                *(uint32_t*)&Vtl[d][i * 16 + jj] = lo;
            }
        }
        // stage K rows hi/lo (token = tid)
        {
            const float* kp = K + ((long)b * TTOK + t0 + tid) * EMBD + h * DHEAD;
            #pragma unroll
            for (int d = 0; d < 16; d += 2) {
                float2 kv = *(const float2*)(kp + d);
                uint32_t hi, lo;
                split2(kv.x, kv.y, hi, lo);
                *(uint32_t*)&Ksh[tid][d] = hi;
                *(uint32_t*)&Ksl[tid][d] = lo;
            }
        }
        __syncthreads();

        #pragma unroll 1
        for (int ntp = 0; ntp < 8; ntp++) {
            uint32_t kh[2][2], kl[2][2];
            #pragma unroll
            for (int half = 0; half < 2; half++) {
                const int tok = (2 * ntp + half) * 8 + g;
                kh[half][0] = *(const uint32_t*)&Ksh[tok][2 * tig];
                kh[half][1] = *(const uint32_t*)&Ksh[tok][8 + 2 * tig];
                kl[half][0] = *(const uint32_t*)&Ksl[tok][2 * tig];
                kl[half][1] = *(const uint32_t*)&Ksl[tok][8 + 2 * tig];
            }
            #pragma unroll
            for (int mt = 0; mt < 2; mt++) {
                uint32_t ph[4], pl[4];
                #pragma unroll
                for (int half = 0; half < 2; half++) {
                    float s[4] = {0.f, 0.f, 0.f, 0.f};
                    mma_bf16(s, qh[mt], kh[half][0], kh[half][1]);
                    mma_bf16(s, qh[mt], kl[half][0], kl[half][1]);
                    mma_bf16(s, ql[mt], kh[half][0], kh[half][1]);
                    const float p0 = __expf(s[0] * 0.25f);
                    const float p1 = __expf(s[1] * 0.25f);
                    const float p2 = __expf(s[2] * 0.25f);
                    const float p3 = __expf(s[3] * 0.25f);
                    lsum[mt][0] += p0 + p1;
                    lsum[mt][1] += p2 + p3;
                    split2(p0, p1, ph[half * 2 + 0], pl[half * 2 + 0]);
                    split2(p2, p3, ph[half * 2 + 1], pl[half * 2 + 1]);
                }
                uint32_t pah[4] = {ph[0], ph[1], ph[2], ph[3]};
                uint32_t pal[4] = {pl[0], pl[1], pl[2], pl[3]};
                #pragma unroll
                for (int dn = 0; dn < 2; dn++) {
                    const int vr = 8 * dn + g;
                    const uint32_t vh0 = *(const uint32_t*)&Vth[vr][ntp * 16 + 2 * tig];
                    const uint32_t vh1 = *(const uint32_t*)&Vth[vr][ntp * 16 + 8 + 2 * tig];
                    const uint32_t vl0 = *(const uint32_t*)&Vtl[vr][ntp * 16 + 2 * tig];
                    const uint32_t vl1 = *(const uint32_t*)&Vtl[vr][ntp * 16 + 8 + 2 * tig];
                    mma_bf16(accO[mt][dn], pah, vh0, vh1);
                    mma_bf16(accO[mt][dn], pah, vl0, vl1);
                    mma_bf16(accO[mt][dn], pal, vh0, vh1);
                }
            }
        }
    }

    #pragma unroll
    for (int mt = 0; mt < 2; mt++) {
        #pragma unroll
        for (int j = 0; j < 2; j++) {
            float v = lsum[mt][j];
            v += __shfl_xor_sync(0xFFFFFFFFu, v, 1);
            v += __shfl_xor_sync(0xFFFFFFFFu, v, 2);
            lsum[mt][j] = v;
        }
    }

    // tail token t = 512 (fp32 exact)
    {
        const float* kp = K + ((long)b * TTOK + 512) * EMBD + h * DHEAD;
        const float2 k0 = *(const float2*)(kp + 2 * tig);
        const float2 k1 = *(const float2*)(kp + 8 + 2 * tig);
        const float* vp = V + ((long)b * TTOK + 512) * EMBD + h * DHEAD;
        #pragma unroll
        for (int mt = 0; mt < 2; mt++) {
            const int rA = r0 + mt * 16 + g;
            const int rB = rA + 8;
            const float* qa = Q + ((long)b * MROWS + rA) * EMBD + h * DHEAD;
            const float* qb = Q + ((long)b * MROWS + rB) * EMBD + h * DHEAD;
            const float2 qa0 = *(const float2*)(qa + 2 * tig);
            const float2 qa1 = *(const float2*)(qa + 8 + 2 * tig);
            const float2 qb0 = *(const float2*)(qb + 2 * tig);
            const float2 qb1 = *(const float2*)(qb + 8 + 2 * tig);
            float dA = qa0.x * k0.x + qa0.y * k0.y + qa1.x * k1.x + qa1.y * k1.y;
            float dB = qb0.x * k0.x + qb0.y * k0.y + qb1.x * k1.x + qb1.y * k1.y;
            dA += __shfl_xor_sync(0xFFFFFFFFu, dA, 1);
            dA += __shfl_xor_sync(0xFFFFFFFFu, dA, 2);
            dB += __shfl_xor_sync(0xFFFFFFFFu, dB, 1);
            dB += __shfl_xor_sync(0xFFFFFFFFu, dB, 2);
            const float pA = __expf(dA * 0.25f);
            const float pB = __expf(dB * 0.25f);
            lsum[mt][0] += pA;
            lsum[mt][1] += pB;
            #pragma unroll
            for (int dn = 0; dn < 2; dn++) {
                const float2 v = *(const float2*)(vp + dn * 8 + 2 * tig);
                accO[mt][dn][0] += pA * v.x;
                accO[mt][dn][1] += pA * v.y;
                accO[mt][dn][2] += pB * v.x;
                accO[mt][dn][3] += pB * v.y;
            }
        }
    }

    #pragma unroll
    for (int mt = 0; mt < 2; mt++) {
        const int rA = r0 + mt * 16 + g;
        const int rB = rA + 8;
        const float invA = 1.0f / lsum[mt][0];
        const float invB = 1.0f / lsum[mt][1];
        float* oa = O + ((long)b * MROWS + rA) * EMBD + h * DHEAD;
        float* ob = O + ((long)b * MROWS + rB) * EMBD + h * DHEAD;
        #pragma unroll
        for (int dn = 0; dn < 2; dn++) {
            *(float2*)(oa + dn * 8 + 2 * tig) =
                make_float2(accO[mt][dn][0] * invA, accO[mt][dn][1] * invA);
            *(float2*)(ob + dn * 8 + 2 * tig) =
                make_float2(accO[mt][dn][2] * invB, accO[mt][dn][3] * invB);
        }
    }
}

// =================== Wc projection (+bias) + MH bf16 split out ==============
#define BK 16
#define BN 128
#define WBM 64
__global__ void __launch_bounds__(256)
wc_kernel(const float* __restrict__ X, const float* __restrict__ W,
          const float* __restrict__ bias, float* __restrict__ C,
          __nv_bfloat16* __restrict__ MHh, __nv_bfloat16* __restrict__ MHl)
{
    __shared__ float As[2][BK][WBM + 4];
    __shared__ float Bs[2][BK][BN];

    const int tid  = threadIdx.x;
    const int row0 = blockIdx.y * WBM;
    const int col0 = blockIdx.x * BN;

    const int a_row = tid >> 2;
    const int a_k   = (tid & 3) * 4;
    const int b_k   = tid >> 4;
    const int b_n   = (tid & 15) * 8;
    const int tx = tid & 15;
    const int ty = tid >> 4;

    const float* xrow = X + (long)(row0 + a_row) * EMBD;
    const float* wptr = W + (long)b_k * EMBD + col0 + b_n;

    float4 av, bv0, bv1;
    av  = *(const float4*)(xrow + a_k);
    bv0 = *(const float4*)(wptr);
    bv1 = *(const float4*)(wptr + 4);
    As[0][a_k+0][a_row]=av.x; As[0][a_k+1][a_row]=av.y;
    As[0][a_k+2][a_row]=av.z; As[0][a_k+3][a_row]=av.w;
    *(float4*)&Bs[0][b_k][b_n]     = bv0;
    *(float4*)&Bs[0][b_k][b_n + 4] = bv1;
    __syncthreads();

    ull acc2[4][4] = {};

    #pragma unroll 1
    for (int ks = 0; ks < EMBD / BK; ks++) {
        const int cur = ks & 1;
        const bool has_next = (ks < EMBD / BK - 1);
        if (has_next) {
            const int k0 = (ks + 1) * BK;
            av  = *(const float4*)(xrow + k0 + a_k);
            bv0 = *(const float4*)(wptr + (long)k0 * EMBD);
            bv1 = *(const float4*)(wptr + (long)k0 * EMBD + 4);
        }
        #pragma unroll
        for (int kk = 0; kk < BK; kk++) {
            float4 a0 = *(const float4*)&As[cur][kk][ty * 4];
            ulonglong2 p0 = *(const ulonglong2*)&Bs[cur][kk][tx * 4];
            ulonglong2 p1 = *(const ulonglong2*)&Bs[cur][kk][64 + tx * 4];
            ull B2[4] = {p0.x, p0.y, p1.x, p1.y};
            float a[4] = {a0.x, a0.y, a0.z, a0.w};
            #pragma unroll
            for (int i = 0; i < 4; i++) {
                const ull ai = bcast2(a[i]);
                #pragma unroll
                for (int j = 0; j < 4; j++)
                    acc2[i][j] = fma2(ai, B2[j], acc2[i][j]);
            }
        }
        if (has_next) {
            const int nxt = 1 - cur;
            As[nxt][a_k+0][a_row]=av.x; As[nxt][a_k+1][a_row]=av.y;
            As[nxt][a_k+2][a_row]=av.z; As[nxt][a_k+3][a_row]=av.w;
            *(float4*)&Bs[nxt][b_k][b_n]     = bv0;
            *(float4*)&Bs[nxt][b_k][b_n + 4] = bv1;
        }
        __syncthreads();
    }

    float4 bb0 = *(const float4*)(bias + col0 + tx * 4);
    float4 bb1 = *(const float4*)(bias + col0 + 64 + tx * 4);

    #pragma unroll
    for (int i = 0; i < 4; i++) {
        const int r = row0 + ty * 4 + i;
        float2 c0 = unpack2(acc2[i][0]);
        float2 c1 = unpack2(acc2[i][1]);
        float2 c2 = unpack2(acc2[i][2]);
        float2 c3 = unpack2(acc2[i][3]);
        float4 o0 = make_float4(c0.x+bb0.x, c0.y+bb0.y, c1.x+bb0.z, c1.y+bb0.w);
        float4 o1 = make_float4(c2.x+bb1.x, c2.y+bb1.y, c3.x+bb1.z, c3.y+bb1.w);
        const long m0 = (long)r * EMBD + col0 + tx * 4;
        const long m1 = (long)r * EMBD + col0 + 64 + tx * 4;
        *(float4*)(C + m0) = o0;
        *(float4*)(C + m1) = o1;
        uint32_t h0, l0, h1, l1;
        split2(o0.x, o0.y, h0, l0); split2(o0.z, o0.w, h1, l1);
        *(uint32_t*)(MHh + m0) = h0; *(uint32_t*)(MHh + m0 + 2) = h1;
        *(uint32_t*)(MHl + m0) = l0; *(uint32_t*)(MHl + m0 + 2) = l1;
        split2(o1.x, o1.y, h0, l0); split2(o1.z, o1.w, h1, l1);
        *(uint32_t*)(MHh + m1) = h0; *(uint32_t*)(MHh + m1 + 2) = h1;
        *(uint32_t*)(MHl + m1) = l0; *(uint32_t*)(MHl + m1 + 2) = l1;
    }
}

// =================== score2: HMMA bf16-split + tanh/exp epilogue ===========
// A = MH[b] (128x256, hi/lo), B = jobs-virtual rows from Xh/Xl.
__global__ void __launch_bounds__(256, 2)
score2_kernel(const __nv_bfloat16* __restrict__ MHh,
              const __nv_bfloat16* __restrict__ MHl,
              const __nv_bfloat16* __restrict__ Xh,
              const __nv_bfloat16* __restrict__ Xl,
              const float* __restrict__ mask,
              float* __restrict__ out, float* __restrict__ sums)
{
    extern __shared__ char smem[];
    __shared__ float red[256];

    const int b    = blockIdx.z;
    const int col0 = blockIdx.x * 128;   // t tile: 0,128,256,384 (t<=511)

    const int tid  = threadIdx.x;
    const int warp = tid >> 5;
    const int lane = tid & 31;
    const int wm = warp & 3;
    const int wn = warp >> 2;
    const int g   = lane >> 2;
    const int tig = lane & 3;

    const int lrow = tid >> 1;
    const int lseg = (tid & 1) * 32;

    float acc[2][8][4] = {};

    #pragma unroll 1
    for (int kc = 0; kc < 4; kc++) {
        const int ko0 = kc * 64;
        {
            const __nv_bfloat16* gAh = MHh + (long)(b * MROWS + lrow) * EMBD + ko0 + lseg;
            const __nv_bfloat16* gAl = MHl + (long)(b * MROWS + lrow) * EMBD + ko0 + lseg;
            const __nv_bfloat16* gBh = Xh + (long)(b * TTOK + col0 + lrow) * EMBD + ko0 + lseg;
            const __nv_bfloat16* gBl = Xl + (long)(b * TTOK + col0 + lrow) * EMBD + ko0 + lseg;
            char* sAh = smem + OFF_AH + lrow * (PADK * 2) + lseg * 2;
            char* sAl = smem + OFF_AL + lrow * (PADK * 2) + lseg * 2;
            char* sBh = smem + OFF_BH + lrow * (PADK * 2) + lseg * 2;
            char* sBl = smem + OFF_BL + lrow * (PADK * 2) + lseg * 2;
            #pragma unroll
            for (int j = 0; j < 4; j++) {
                *(uint4*)(sAh + j * 16) = *(const uint4*)(gAh + j * 8);
                *(uint4*)(sAl + j * 16) = *(const uint4*)(gAl + j * 8);
                *(uint4*)(sBh + j * 16) = *(const uint4*)(gBh + j * 8);
                *(uint4*)(sBl + j * 16) = *(const uint4*)(gBl + j * 8);
            }
        }
        __syncthreads();

        #pragma unroll
        for (int ks = 0; ks < 4; ks++) {
            const int ko = ks * 16;
            uint32_t ahf[2][4], alf[2][4];
            #pragma unroll
            for (int mt = 0; mt < 2; mt++) {
                const int r0 = wm * 32 + mt * 16 + g;
                const char* bAh = smem + OFF_AH;
                const char* bAl = smem + OFF_AL;
                const int c0 = (ko + 2 * tig) * 2;
                const int c8 = (ko + 8 + 2 * tig) * 2;
                ahf[mt][0] = *(const uint32_t*)(bAh + r0 * (PADK*2) + c0);
                ahf[mt][1] = *(const uint32_t*)(bAh + (r0+8) * (PADK*2) + c0);
                ahf[mt][2] = *(const uint32_t*)(bAh + r0 * (PADK*2) + c8);
                ahf[mt][3] = *(const uint32_t*)(bAh + (r0+8) * (PADK*2) + c8);
                alf[mt][0] = *(const uint32_t*)(bAl + r0 * (PADK*2) + c0);
                alf[mt][1] = *(const uint32_t*)(bAl + (r0+8) * (PADK*2) + c0);
                alf[mt][2] = *(const uint32_t*)(bAl + r0 * (PADK*2) + c8);
                alf[mt][3] = *(const uint32_t*)(bAl + (r0+8) * (PADK*2) + c8);
            }
            #pragma unroll
            for (int nt = 0; nt < 8; nt++) {
                const int nr = wn * 64 + nt * 8 + g;
                const char* bBh = smem + OFF_BH;
                const char* bBl = smem + OFF_BL;
                const int c0 = (ko + 2 * tig) * 2;
                const int c8 = (ko + 8 + 2 * tig) * 2;
                const uint32_t bh0 = *(const uint32_t*)(bBh + nr * (PADK*2) + c0);
                const uint32_t bh1 = *(const uint32_t*)(bBh + nr * (PADK*2) + c8);
                const uint32_t bl0 = *(const uint32_t*)(bBl + nr * (PADK*2) + c0);
                const uint32_t bl1 = *(const uint32_t*)(bBl + nr * (PADK*2) + c8);
                #pragma unroll
                for (int mt = 0; mt < 2; mt++) {
                    mma_bf16(acc[mt][nt], ahf[mt], bh0, bh1);
                    mma_bf16(acc[mt][nt], ahf[mt], bl0, bl1);
                    mma_bf16(acc[mt][nt], alf[mt], bh0, bh1);
                }
            }
        }
        __syncthreads();
    }

    // epilogue: tanh/exp/mask; odd stride -> scalar stores
    float lsum = 0.0f;
    #pragma unroll
    for (int mt = 0; mt < 2; mt++) {
        const int r_lo = wm * 32 + mt * 16 + g;
        const int r_hi = r_lo + 8;
        const long base_lo = (long)b * OUT_PER_B + (long)r_lo * TTOK;
        const long base_hi = (long)b * OUT_PER_B + (long)r_hi * TTOK;
        #pragma unroll
        for (int nt = 0; nt < 8; nt++) {
            const int t = col0 + wn * 64 + nt * 8 + 2 * tig;
            const float y0 = __expf(10.0f * tanh_fast(acc[mt][nt][0] * 0.0625f) + mask[base_lo + t]);
            const float y1 = __expf(10.0f * tanh_fast(acc[mt][nt][1] * 0.0625f) + mask[base_lo + t + 1]);
            const float y2 = __expf(10.0f * tanh_fast(acc[mt][nt][2] * 0.0625f) + mask[base_hi + t]);
            const float y3 = __expf(10.0f * tanh_fast(acc[mt][nt][3] * 0.0625f) + mask[base_hi + t + 1]);
            out[base_lo + t]     = y0;
            out[base_lo + t + 1] = y1;
            out[base_hi + t]     = y2;
            out[base_hi + t + 1] = y3;
            lsum += y0 + y1 + y2 + y3;
        }
    }

    red[tid] = lsum;
    __syncthreads();
    #pragma unroll
    for (int s = 128; s > 0; s >>= 1) {
        if (tid < s) red[tid] += red[tid + s];
        __syncthreads();
    }
    if (tid == 0) atomicAdd(&sums[b], red[0]);
}

// =================== t=512 column tail ================
__global__ void __launch_bounds__(128)
tail_kernel(const float* __restrict__ MH, const float* __restrict__ jobs,
            const float* __restrict__ mask, float* __restrict__ out,
            float* __restrict__ sums)
{
    __shared__ float jrow[EMBD];
    __shared__ float red[128];

    const int b = blockIdx.x;
    const int m = threadIdx.x;

    const float* jr = jobs + ((long)b * JJOBS + 511) * EMBD;
    *(float2*)&jrow[m * 2] = *(const float2*)(jr + m * 2);
    __syncthreads();

    const float* mh = MH + ((long)b * MROWS + m) * EMBD;
    ull d2 = bcast2(0.0f);
    #pragma unroll
    for (int k = 0; k < EMBD; k += 8) {
        ulonglong2 a = *(const ulonglong2*)(mh + k);
        ulonglong2 a2 = *(const ulonglong2*)(mh + k + 4);
        ulonglong2 w = *(const ulonglong2*)&jrow[k];
        ulonglong2 w2 = *(const ulonglong2*)&jrow[k + 4];
        d2 = fma2(a.x, w.x, d2);
        d2 = fma2(a.y, w.y, d2);
        d2 = fma2(a2.x, w2.x, d2);
        d2 = fma2(a2.y, w2.y, d2);
    }
    float2 f = unpack2(d2);
    const float sc = (f.x + f.y) * 0.0625f;
    const long li = (long)b * OUT_PER_B + (long)m * TTOK + 512;
    const float y = __expf(10.0f * tanh_fast(sc) + mask[li]);
    out[li] = y;

    red[m] = y;
    __syncthreads();
    #pragma unroll
    for (int s = 64; s > 0; s >>= 1) {
        if (m < s) red[m] += red[m + s];
        __syncthreads();
    }
    if (m == 0) atomicAdd(&sums[b], red[0]);
}

// =================== normalize =======================
__global__ void __launch_bounds__(256)
norm_kernel(float4* __restrict__ out, const float* __restrict__ sums)
{
    const int b = blockIdx.y;
    const long per_b4 = OUT_PER_B / 4;
    const long idx = (long)blockIdx.x * blockDim.x + threadIdx.x;
    if (idx < per_b4) {
        const float inv = 1.0f / sums[b];
        float4 v = out[(long)b * per_b4 + idx];
        v.x *= inv; v.y *= inv; v.z *= inv; v.w *= inv;
        out[(long)b * per_b4 + idx] = v;
    }
}

// =================== launch ===================
extern "C" void kernel_launch(void* const* d_in, const int* in_sizes, int n_in,
                              void* d_out, int out_size)
{
    const float* machine = (const float*)d_in[0];
    const float* jobs    = (const float*)d_in[1];
    const float* mask    = (const float*)d_in[2];
    const float* Wq3     = (const float*)d_in[3];
    const float* Wk      = (const float*)d_in[4];
    const float* Wv      = (const float*)d_in[5];
    const float* Wc      = (const float*)d_in[6];
    const float* bc      = (const float*)d_in[7];
    const float* skip    = (const float*)d_in[8];
    float* out = (float*)d_out;

    float *Qp, *Kp, *Vp, *Op, *MHp, *Sp;
    __nv_bfloat16 *Xh, *Xl, *Wh, *Wl, *MHh, *MHl;
    cudaGetSymbolAddress((void**)&Qp,  g_Q);
    cudaGetSymbolAddress((void**)&Kp,  g_K);
    cudaGetSymbolAddress((void**)&Vp,  g_V);
    cudaGetSymbolAddress((void**)&Op,  g_O);
    cudaGetSymbolAddress((void**)&MHp, g_MH);
    cudaGetSymbolAddress((void**)&Sp,  g_SUM);
    cudaGetSymbolAddress((void**)&Xh,  g_Xh);
    cudaGetSymbolAddress((void**)&Xl,  g_Xl);
    cudaGetSymbolAddress((void**)&Wh,  g_Wh);
    cudaGetSymbolAddress((void**)&Wl,  g_Wl);
    cudaGetSymbolAddress((void**)&MHh, g_MHh);
    cudaGetSymbolAddress((void**)&MHl, g_MHl);

    cudaFuncSetAttribute(proj_wmma_kernel,
                         cudaFuncAttributeMaxDynamicSharedMemorySize, PROJ_SMEM);
    cudaFuncSetAttribute(score2_kernel,
                         cudaFuncAttributeMaxDynamicSharedMemorySize, PROJ_SMEM);

    convert_w_kernel<<<dim3(8, 8, 3), 256>>>(Wk, Wv, Wq3, Wh, Wl);
    {
        const long total = (long)XROWS * 32;
        convert_x_kernel<<<(int)((total + 255) / 256), 256>>>(
            jobs, skip, machine, Xh, Xl, Sp);
    }

    proj_wmma_kernel<<<dim3(2, 257, 3), 256, PROJ_SMEM>>>(
        Xh, Xl, Wh, Wl, Kp, Vp, Qp);

    attn_kernel<<<dim3(HEADS, BATCH), 128>>>(Qp, Kp, Vp, Op);

    wc_kernel<<<dim3(EMBD / BN, (BATCH * MROWS) / WBM), 256>>>(
        Op, Wc, bc, MHp, MHh, MHl);

    score2_kernel<<<dim3(4, 1, BATCH), 256, PROJ_SMEM>>>(
        MHh, MHl, Xh, Xl, mask, out, Sp);
    tail_kernel<<<BATCH, 128>>>(MHp, jobs, mask, out, Sp);

    const int per_b4 = OUT_PER_B / 4;
    norm_kernel<<<dim3((per_b4 + 255) / 256, BATCH), 256>>>((float4*)out, Sp);
}